// round 1
// baseline (speedup 1.0000x reference)
#include <cuda_runtime.h>
#include <math.h>

#define Bq 8
#define Lq 128
#define Bp 64
#define Lp 512
#define Hd 1024
#define MQ (Bq*(Lq-1))   /* 1016  */
#define MP (Bp*(Lp-1))   /* 32704 */
#define INV_TEMP 50.0f

/* ---------------- scratch (allocation-free: device globals) ---------------- */
__device__ float g_tw_q[Bq*Lq];
__device__ float g_wq[Bq*Lq];
__device__ float g_tw_p[Bp*Lp];
__device__ float g_wp[Bp*Lp];
__device__ float g_Qc[(size_t)MQ*Hd];
__device__ float g_Pc[(size_t)MP*Hd];
__device__ float g_S[(size_t)MQ*MP];
__device__ float g_qmax[MQ*Bp];

/* ---------------- dense: CLS cosine / TEMP ---------------- */
__global__ void dense_kernel(const float* __restrict__ qh, const float* __restrict__ ph,
                             float* __restrict__ out)
{
    int pb = blockIdx.x, qb = blockIdx.y, tid = threadIdx.x;
    const float* q = qh + (long)qb*Lq*Hd;   // row 0 = CLS
    const float* p = ph + (long)pb*Lp*Hd;
    float qq=0.f, pp=0.f, qp=0.f;
    for (int i=tid;i<Hd;i+=256){ float a=q[i], b=p[i];
        qq=fmaf(a,a,qq); pp=fmaf(b,b,pp); qp=fmaf(a,b,qp); }
    __shared__ float r0[256], r1[256], r2[256];
    r0[tid]=qq; r1[tid]=pp; r2[tid]=qp; __syncthreads();
    for (int o=128;o>0;o>>=1){
        if (tid<o){ r0[tid]+=r0[tid+o]; r1[tid]+=r1[tid+o]; r2[tid]+=r2[tid+o]; }
        __syncthreads();
    }
    if (tid==0){
        float d = fmaxf(sqrtf(r0[0]),1e-12f)*fmaxf(sqrtf(r1[0]),1e-12f);
        out[qb*Bp+pb] = r2[0]/d*INV_TEMP;
    }
}

/* ---------------- sparse: token weights (warp per token) ---------------- */
__global__ void tw_kernel(const float* __restrict__ hidden, const float* __restrict__ sw,
                          const float* __restrict__ sbp, float* __restrict__ tw, int total)
{
    int w = (blockIdx.x*blockDim.x + threadIdx.x) >> 5;
    int lane = threadIdx.x & 31;
    if (w >= total) return;
    const float* h = hidden + (long)w*Hd;
    float s = 0.f;
    for (int i=lane;i<Hd;i+=32) s = fmaf(h[i], sw[i], s);
    #pragma unroll
    for (int o=16;o;o>>=1) s += __shfl_xor_sync(0xffffffffu, s, o);
    if (lane==0) tw[w] = fmaxf(s + sbp[0], 0.f);
}

/* canonical-occurrence dedup: weight kept only for the first index achieving
   the per-id max within a batch; unused ids {0,1,2,3} zeroed. */
__global__ void canon_kernel(const int* __restrict__ ids, const float* __restrict__ tw,
                             float* __restrict__ weff, int L)
{
    __shared__ int   sid[512];
    __shared__ float stw[512];
    int b = blockIdx.x, i = threadIdx.x;
    int base = b*L;
    sid[i] = ids[base+i]; stw[i] = tw[base+i];
    __syncthreads();
    float w = stw[i]; int id = sid[i];
    if (id < 4) w = 0.f;
    else {
        for (int j=0;j<L;j++){
            if (j!=i && sid[j]==id){
                float wj = stw[j];
                if (wj > w || (wj==w && j<i)) { w=0.f; break; }
            }
        }
    }
    weff[base+i] = w;
}

__global__ void sparse_score_kernel(const int* __restrict__ q_ids, const float* __restrict__ wq,
                                    const int* __restrict__ p_ids, const float* __restrict__ wp,
                                    float* __restrict__ out)
{
    __shared__ int   spid[Lp];
    __shared__ float spw[Lp];
    __shared__ float red[256];
    int pb=blockIdx.x, qb=blockIdx.y, tid=threadIdx.x;
    for (int j=tid;j<Lp;j+=256){ spid[j]=p_ids[pb*Lp+j]; spw[j]=wp[pb*Lp+j]; }
    __syncthreads();
    float s = 0.f;
    if (tid < Lq){
        int id = q_ids[qb*Lq+tid]; float w = wq[qb*Lq+tid];
        if (w > 0.f){
            for (int j=0;j<Lp;j++) if (spid[j]==id) s = fmaf(w, spw[j], s);
        }
    }
    red[tid]=s; __syncthreads();
    for (int o=128;o>0;o>>=1){ if (tid<o) red[tid]+=red[tid+o]; __syncthreads(); }
    if (tid==0) out[Bq*Bp + qb*Bp+pb] = red[0]*INV_TEMP;
}

/* ---------------- SGEMM NT: C[M,N] = A[M,K] * B[N,K]^T ----------------
   A optionally gathered: if La>0, logical row r maps to source row
   (r/(La-1))*La + r%(La-1) + 1   (drops CLS token per batch).          */
#define BM 128
#define BN 64
#define BK 16

__global__ void sgemm_nt(const float* __restrict__ A, const float* __restrict__ B,
                         float* __restrict__ C, int M, int N, int K, int La)
{
    __shared__ float As[BK][BM];
    __shared__ float Bs[BK][BN];
    int tid = threadIdx.x;            // 256 threads
    int ty = tid >> 4, tx = tid & 15; // 16x16; 8 rows x 4 cols per thread
    int brow = blockIdx.y, bcol = blockIdx.x;

    // A tile loader: each thread owns 8 contiguous k of one row
    int ar = tid >> 1;                 // 0..127
    int ak = (tid & 1) * 8;
    int arow = brow*BM + ar;
    bool avalid = (arow < M);
    const float* aptr = A;
    if (avalid){
        long srow = arow;
        if (La > 0){ int Lm1 = La-1; srow = (long)(arow/Lm1)*La + (arow%Lm1) + 1; }
        aptr = A + srow*(long)K + ak;
    }
    // B tile loader: 4 contiguous k of one row; N is always a multiple of 64
    int br = tid >> 2;
    int bk = (tid & 3) * 4;
    const float* bptr = B + ((long)(bcol*BN + br))*K + bk;

    float acc[8][4];
    #pragma unroll
    for (int i=0;i<8;i++)
        #pragma unroll
        for (int j=0;j<4;j++) acc[i][j]=0.f;

    for (int k0=0;k0<K;k0+=BK){
        float4 a0 = make_float4(0,0,0,0), a1 = make_float4(0,0,0,0);
        if (avalid){
            a0 = *(const float4*)(aptr + k0);
            a1 = *(const float4*)(aptr + k0 + 4);
        }
        As[ak+0][ar]=a0.x; As[ak+1][ar]=a0.y; As[ak+2][ar]=a0.z; As[ak+3][ar]=a0.w;
        As[ak+4][ar]=a1.x; As[ak+5][ar]=a1.y; As[ak+6][ar]=a1.z; As[ak+7][ar]=a1.w;
        float4 bv = *(const float4*)(bptr + k0);
        Bs[bk+0][br]=bv.x; Bs[bk+1][br]=bv.y; Bs[bk+2][br]=bv.z; Bs[bk+3][br]=bv.w;
        __syncthreads();
        #pragma unroll
        for (int k=0;k<BK;k++){
            float a[8], b[4];
            *(float4*)(a)   = *(const float4*)&As[k][ty*8];
            *(float4*)(a+4) = *(const float4*)&As[k][ty*8+4];
            *(float4*)(b)   = *(const float4*)&Bs[k][tx*4];
            #pragma unroll
            for (int i=0;i<8;i++)
                #pragma unroll
                for (int j=0;j<4;j++)
                    acc[i][j] = fmaf(a[i], b[j], acc[i][j]);
        }
        __syncthreads();
    }
    int ccol = bcol*BN + tx*4;
    #pragma unroll
    for (int i=0;i<8;i++){
        int row = brow*BM + ty*8 + i;
        if (row < M){
            float4 v = make_float4(acc[i][0],acc[i][1],acc[i][2],acc[i][3]);
            *(float4*)(C + (long)row*N + ccol) = v;
        }
    }
}

/* ---------------- bias + mask + L2-normalize rows in place ---------------- */
__global__ void bias_mask_norm_kernel(float* __restrict__ C, const float* __restrict__ bias,
                                      const float* __restrict__ mask, int L)
{
    int row = blockIdx.x, tid = threadIdx.x;   // 256 threads, 1024 cols
    float* c = C + (long)row*Hd;
    int Lm1 = L-1;
    float m = mask[(row/Lm1)*L + (row%Lm1) + 1];
    float v[4]; float ss = 0.f;
    #pragma unroll
    for (int k=0;k<4;k++){ int i = tid + k*256; v[k]=(c[i]+bias[i])*m; ss = fmaf(v[k],v[k],ss); }
    __shared__ float red[256];
    red[tid]=ss; __syncthreads();
    for (int o=128;o>0;o>>=1){ if (tid<o) red[tid]+=red[tid+o]; __syncthreads(); }
    float inv = 1.0f / fmaxf(sqrtf(red[0]), 1e-12f);
    #pragma unroll
    for (int k=0;k<4;k++){ int i = tid + k*256; c[i] = v[k]*inv; }
}

/* ---------------- colbert: per (q-row, pb) max over passage tokens ---------------- */
__global__ void rowmax_kernel(const float* __restrict__ S, float* __restrict__ qmax)
{
    int qr = blockIdx.x;              // 0..MQ-1
    int tid = threadIdx.x;            // 512 threads = 16 warps
    int warp = tid >> 5, lane = tid & 31;
    #pragma unroll
    for (int it=0; it<4; it++){
        int pb = warp + it*16;
        const float* s = S + (long)qr*MP + (long)pb*(Lp-1);
        float m = -1e30f;
        for (int j=lane;j<(Lp-1);j+=32) m = fmaxf(m, s[j]);
        #pragma unroll
        for (int o=16;o;o>>=1) m = fmaxf(m, __shfl_xor_sync(0xffffffffu, m, o));
        if (lane==0) qmax[qr*Bp + pb] = m;
    }
}

__global__ void colbert_final_kernel(const float* __restrict__ qmax,
                                     const float* __restrict__ q_mask,
                                     float* __restrict__ out)
{
    int pb=blockIdx.x, qb=blockIdx.y, tid=threadIdx.x;  // 128 threads
    float v=0.f, mm=0.f;
    if (tid < Lq-1){
        v  = qmax[(qb*(Lq-1)+tid)*Bp + pb];
        mm = q_mask[qb*Lq + tid + 1];
    }
    __shared__ float rv[128], rm[128];
    rv[tid]=v; rm[tid]=mm; __syncthreads();
    for (int o=64;o>0;o>>=1){ if (tid<o){ rv[tid]+=rv[tid+o]; rm[tid]+=rm[tid+o]; } __syncthreads(); }
    if (tid==0) out[2*Bq*Bp + qb*Bp+pb] = rv[0]/rm[0]*INV_TEMP;
}

/* ---------------- launcher ---------------- */
extern "C" void kernel_launch(void* const* d_in, const int* in_sizes, int n_in,
                              void* d_out, int out_size)
{
    const float* q_hidden  = (const float*)d_in[0];
    const float* p_hidden  = (const float*)d_in[1];
    const float* q_mask    = (const float*)d_in[2];
    const float* p_mask    = (const float*)d_in[3];
    const int*   q_ids     = (const int*)  d_in[4];
    const int*   p_ids     = (const int*)  d_in[5];
    const float* colbert_w = (const float*)d_in[6];
    const float* colbert_b = (const float*)d_in[7];
    const float* sparse_w  = (const float*)d_in[8];
    const float* sparse_b  = (const float*)d_in[9];
    float* out = (float*)d_out;

    static float *p_tw_q=nullptr,*p_wq=nullptr,*p_tw_p=nullptr,*p_wp=nullptr,
                 *p_Qc=nullptr,*p_Pc=nullptr,*p_S=nullptr,*p_qmax=nullptr;
    if (!p_tw_q){
        cudaGetSymbolAddress((void**)&p_tw_q, g_tw_q);
        cudaGetSymbolAddress((void**)&p_wq,   g_wq);
        cudaGetSymbolAddress((void**)&p_tw_p, g_tw_p);
        cudaGetSymbolAddress((void**)&p_wp,   g_wp);
        cudaGetSymbolAddress((void**)&p_Qc,   g_Qc);
        cudaGetSymbolAddress((void**)&p_Pc,   g_Pc);
        cudaGetSymbolAddress((void**)&p_S,    g_S);
        cudaGetSymbolAddress((void**)&p_qmax, g_qmax);
    }

    dim3 gQP(Bp, Bq);

    /* dense */
    dense_kernel<<<gQP, 256>>>(q_hidden, p_hidden, out);

    /* sparse */
    tw_kernel<<<(Bq*Lq*32+255)/256, 256>>>(q_hidden, sparse_w, sparse_b, p_tw_q, Bq*Lq);
    tw_kernel<<<(Bp*Lp*32+255)/256, 256>>>(p_hidden, sparse_w, sparse_b, p_tw_p, Bp*Lp);
    canon_kernel<<<Bq, Lq>>>(q_ids, p_tw_q, p_wq, Lq);
    canon_kernel<<<Bp, Lp>>>(p_ids, p_tw_p, p_wp, Lp);
    sparse_score_kernel<<<gQP, 256>>>(q_ids, p_wq, p_ids, p_wp, out);

    /* colbert: projections (drop CLS via gather), then normalize */
    sgemm_nt<<<dim3(Hd/BN, (MQ+BM-1)/BM), 256>>>(q_hidden, colbert_w, p_Qc, MQ, Hd, Hd, Lq);
    sgemm_nt<<<dim3(Hd/BN, (MP+BM-1)/BM), 256>>>(p_hidden, colbert_w, p_Pc, MP, Hd, Hd, Lp);
    bias_mask_norm_kernel<<<MQ, 256>>>(p_Qc, colbert_b, q_mask, Lq);
    bias_mask_norm_kernel<<<MP, 256>>>(p_Pc, colbert_b, p_mask, Lp);

    /* colbert: token-score GEMM + maxsim reduce */
    sgemm_nt<<<dim3(MP/BN, (MQ+BM-1)/BM), 256>>>(p_Qc, p_Pc, p_S, MQ, MP, Hd, 0);
    rowmax_kernel<<<MQ, 512>>>(p_S, p_qmax);
    colbert_final_kernel<<<gQP, 128>>>(p_qmax, q_mask, out);
}

// round 2
// speedup vs baseline: 3.6480x; 3.6480x over previous
#include <cuda_runtime.h>
#include <cuda_bf16.h>
#include <math.h>

#define Bq 8
#define Lq 128
#define Bp 64
#define Lp 512
#define Hd 1024
#define MQ (Bq*(Lq-1))   /* 1016  */
#define MP (Bp*(Lp-1))   /* 32704 */
#define INV_TEMP 50.0f

#define SA 56            /* padded smem row stride (bf16 elems): conflict-free ldmatrix */
#define AS_ELE (128*SA)
#define BS_ELE (64*SA)

/* ---------------- scratch (allocation-free: device globals) ---------------- */
__device__ float g_tw_q[Bq*Lq];
__device__ float g_wq[Bq*Lq];
__device__ float g_tw_p[Bp*Lp];
__device__ float g_wp[Bp*Lp];
__device__ float g_Qc[(size_t)MQ*Hd];
__device__ float g_Pc[(size_t)MP*Hd];
__device__ float g_qmax[MQ*Bp];
__device__ __nv_bfloat16 g_qh_bf[(size_t)Bq*Lq*Hd];
__device__ __nv_bfloat16 g_ph_bf[(size_t)Bp*Lp*Hd];
__device__ __nv_bfloat16 g_w_bf[(size_t)Hd*Hd];
__device__ __nv_bfloat16 g_Qcb[(size_t)MQ*Hd];
__device__ __nv_bfloat16 g_Pcb[(size_t)MP*Hd];

/* ---------------- mma helpers ---------------- */
__device__ __forceinline__ void mma_bf16(float* c, const unsigned* a, const unsigned* b){
    asm volatile("mma.sync.aligned.m16n8k16.row.col.f32.bf16.bf16.f32 "
        "{%0,%1,%2,%3}, {%4,%5,%6,%7}, {%8,%9}, {%0,%1,%2,%3};"
        : "+f"(c[0]), "+f"(c[1]), "+f"(c[2]), "+f"(c[3])
        : "r"(a[0]), "r"(a[1]), "r"(a[2]), "r"(a[3]), "r"(b[0]), "r"(b[1]));
}
__device__ __forceinline__ void ldm_x4(unsigned& r0, unsigned& r1, unsigned& r2, unsigned& r3, unsigned addr){
    asm volatile("ldmatrix.sync.aligned.m8n8.x4.shared.b16 {%0,%1,%2,%3}, [%4];"
        : "=r"(r0), "=r"(r1), "=r"(r2), "=r"(r3) : "r"(addr));
}
__device__ __forceinline__ void ldm_x2(unsigned& r0, unsigned& r1, unsigned addr){
    asm volatile("ldmatrix.sync.aligned.m8n8.x2.shared.b16 {%0,%1}, [%2];"
        : "=r"(r0), "=r"(r1) : "r"(addr));
}

/* one K=32 smem stage: 2 mma k-steps, warp tile 32x32 (2 mtiles x 4 ntiles) */
__device__ __forceinline__ void mma_stage(unsigned as_buf, unsigned bs_buf,
                                          int lane, int wm, int wn, float acc[2][4][4])
{
    #pragma unroll
    for (int step=0; step<2; step++){
        int klo = step*16;
        unsigned a[2][4], b[4][2];
        int m_i = lane>>3;
        int arow = ((m_i&1)<<3) + (lane&7);
        int acol = klo + ((m_i>>1)<<3);
        #pragma unroll
        for (int mt=0; mt<2; mt++){
            unsigned addr = as_buf + (unsigned)(((wm*32 + mt*16 + arow)*SA + acol)*2);
            ldm_x4(a[mt][0], a[mt][1], a[mt][2], a[mt][3], addr);
        }
        int li = lane&15;
        int brow = li&7;
        int bcol = klo + ((li>>3)<<3);
        #pragma unroll
        for (int nt=0; nt<4; nt++){
            unsigned addr = bs_buf + (unsigned)(((wn*32 + nt*8 + brow)*SA + bcol)*2);
            ldm_x2(b[nt][0], b[nt][1], addr);
        }
        #pragma unroll
        for (int mt=0; mt<2; mt++)
            #pragma unroll
            for (int nt=0; nt<4; nt++)
                mma_bf16(acc[mt][nt], a[mt], b[nt]);
    }
}

__device__ __forceinline__ uint4 ldg16_or0(const __nv_bfloat16* p, bool v){
    uint4 z = make_uint4(0,0,0,0);
    if (v) z = *(const uint4*)p;
    return z;
}

/* ---------------- f32 -> bf16 convert ---------------- */
__global__ void f2bf_kernel(const float* __restrict__ in, __nv_bfloat16* __restrict__ out, int n4){
    int i = blockIdx.x*blockDim.x + threadIdx.x;
    if (i < n4){
        float4 v = *(const float4*)(in + (size_t)i*4);
        __nv_bfloat162 lo = __floats2bfloat162_rn(v.x, v.y);
        __nv_bfloat162 hi = __floats2bfloat162_rn(v.z, v.w);
        uint2 o; o.x = *(unsigned*)&lo; o.y = *(unsigned*)&hi;
        *(uint2*)(out + (size_t)i*4) = o;
    }
}

/* ---------------- projection GEMM: C[M,1024] = gather(A)[M,1024] * W^T ----------------
   A: bf16 hidden [B*L][1024]; logical row r -> src (r/(L-1))*L + r%(L-1) + 1 (drop CLS) */
__global__ void proj_gemm(const __nv_bfloat16* __restrict__ A, const __nv_bfloat16* __restrict__ W,
                          float* __restrict__ C, int M, int La)
{
    __shared__ __nv_bfloat16 As[2][AS_ELE];
    __shared__ __nv_bfloat16 Bs[2][BS_ELE];
    int tid = threadIdx.x, lane = tid&31, wid = tid>>5;
    int wm = wid>>1, wn = wid&1;
    int brow = blockIdx.y, bcol = blockIdx.x;

    /* A loader: 2 rows per thread, 8 contiguous k each */
    int ar0 = tid>>2, ak0 = (tid&3)*8;
    int ar1 = ar0 + 64;
    int Lm1 = La - 1;
    int r0 = brow*128 + ar0, r1 = brow*128 + ar1;
    bool v0 = r0 < M, v1 = r1 < M;
    const __nv_bfloat16* ap0 = A;
    const __nv_bfloat16* ap1 = A;
    if (v0) ap0 = A + ((size_t)(r0/Lm1)*La + r0%Lm1 + 1)*Hd + ak0;
    if (v1) ap1 = A + ((size_t)(r1/Lm1)*La + r1%Lm1 + 1)*Hd + ak0;
    /* B loader: 1 row per thread */
    int br = tid>>2, bk = (tid&3)*8;
    const __nv_bfloat16* bp = W + ((size_t)(bcol*64 + br))*Hd + bk;

    unsigned as0 = (unsigned)__cvta_generic_to_shared(&As[0][0]);
    unsigned bs0 = (unsigned)__cvta_generic_to_shared(&Bs[0][0]);

    float acc[2][4][4];
    #pragma unroll
    for (int mt=0;mt<2;mt++) for (int nt=0;nt<4;nt++) for (int j=0;j<4;j++) acc[mt][nt][j]=0.f;

    /* preload stage 0 */
    {
        uint4 a0 = ldg16_or0(ap0, v0), a1 = ldg16_or0(ap1, v1);
        uint4 bv = *(const uint4*)bp;
        *(uint4*)&As[0][ar0*SA + ak0] = a0;
        *(uint4*)&As[0][ar1*SA + ak0] = a1;
        *(uint4*)&Bs[0][br*SA + bk]   = bv;
    }
    __syncthreads();

    const int NST = Hd/32;
    for (int s=0; s<NST; s++){
        int buf = s&1;
        uint4 na0, na1, nb;
        if (s+1 < NST){
            int k0 = (s+1)*32;
            na0 = ldg16_or0(ap0 + k0, v0);
            na1 = ldg16_or0(ap1 + k0, v1);
            nb  = *(const uint4*)(bp + k0);
        }
        mma_stage(as0 + buf*(AS_ELE*2), bs0 + buf*(BS_ELE*2), lane, wm, wn, acc);
        if (s+1 < NST){
            int nb_ = (s+1)&1;
            *(uint4*)&As[nb_][ar0*SA + ak0] = na0;
            *(uint4*)&As[nb_][ar1*SA + ak0] = na1;
            *(uint4*)&Bs[nb_][br*SA + bk]   = nb;
        }
        __syncthreads();
    }

    /* epilogue: fp32 store */
    #pragma unroll
    for (int mt=0;mt<2;mt++){
        int gr = brow*128 + wm*32 + mt*16 + (lane>>2);
        #pragma unroll
        for (int nt=0;nt<4;nt++){
            int gc = bcol*64 + wn*32 + nt*8 + 2*(lane&3);
            if (gr < M)   *(float2*)(C + (size_t)gr*Hd + gc)     = make_float2(acc[mt][nt][0], acc[mt][nt][1]);
            if (gr+8 < M) *(float2*)(C + (size_t)(gr+8)*Hd + gc) = make_float2(acc[mt][nt][2], acc[mt][nt][3]);
        }
    }
}

/* ---------------- fused maxsim GEMM: per (q-tile, passage) running row-max ---------------- */
__global__ void maxsim_gemm(const __nv_bfloat16* __restrict__ Qcb, const __nv_bfloat16* __restrict__ Pcb,
                            float* __restrict__ qmax)
{
    __shared__ __nv_bfloat16 As[2][AS_ELE];
    __shared__ __nv_bfloat16 Bs[2][BS_ELE];
    __shared__ float red[128][2];
    int tid = threadIdx.x, lane = tid&31, wid = tid>>5;
    int wm = wid>>1, wn = wid&1;
    int pb = blockIdx.x, qtile = blockIdx.y;

    int ar0 = tid>>2, ak0 = (tid&3)*8;
    int ar1 = ar0 + 64;
    int r0 = qtile*128 + ar0, r1 = qtile*128 + ar1;
    bool v0 = r0 < MQ, v1 = r1 < MQ;
    const __nv_bfloat16* ap0 = Qcb + (v0 ? (size_t)r0*Hd + ak0 : 0);
    const __nv_bfloat16* ap1 = Qcb + (v1 ? (size_t)r1*Hd + ak0 : 0);
    int br = tid>>2, bk = (tid&3)*8;

    unsigned as0 = (unsigned)__cvta_generic_to_shared(&As[0][0]);
    unsigned bs0 = (unsigned)__cvta_generic_to_shared(&Bs[0][0]);

    float runmax[2][2];
    runmax[0][0]=runmax[0][1]=runmax[1][0]=runmax[1][1]=-1e30f;

    const int NST = Hd/32;
    for (int chunk=0; chunk<8; chunk++){
        int t = chunk*64 + br;
        bool bv = t < (Lp-1);
        const __nv_bfloat16* bp = Pcb + (bv ? ((size_t)pb*(Lp-1) + t)*Hd + bk : 0);

        float acc[2][4][4];
        #pragma unroll
        for (int mt=0;mt<2;mt++) for (int nt=0;nt<4;nt++) for (int j=0;j<4;j++) acc[mt][nt][j]=0.f;

        {
            uint4 a0 = ldg16_or0(ap0, v0), a1 = ldg16_or0(ap1, v1);
            uint4 b0 = ldg16_or0(bp, bv);
            *(uint4*)&As[0][ar0*SA + ak0] = a0;
            *(uint4*)&As[0][ar1*SA + ak0] = a1;
            *(uint4*)&Bs[0][br*SA + bk]   = b0;
        }
        __syncthreads();
        for (int s=0; s<NST; s++){
            int buf = s&1;
            uint4 na0, na1, nb;
            if (s+1 < NST){
                int k0 = (s+1)*32;
                na0 = ldg16_or0(ap0 + k0, v0);
                na1 = ldg16_or0(ap1 + k0, v1);
                nb  = ldg16_or0(bp + k0, bv);
            }
            mma_stage(as0 + buf*(AS_ELE*2), bs0 + buf*(BS_ELE*2), lane, wm, wn, acc);
            if (s+1 < NST){
                int nb_ = (s+1)&1;
                *(uint4*)&As[nb_][ar0*SA + ak0] = na0;
                *(uint4*)&As[nb_][ar1*SA + ak0] = na1;
                *(uint4*)&Bs[nb_][br*SA + bk]   = nb;
            }
            __syncthreads();
        }
        /* fold chunk into running row-max (mask invalid passage tokens) */
        #pragma unroll
        for (int mt=0;mt<2;mt++){
            #pragma unroll
            for (int nt=0;nt<4;nt++){
                int c0 = chunk*64 + wn*32 + nt*8 + 2*(lane&3);
                if (c0 < Lp-1){
                    runmax[mt][0] = fmaxf(runmax[mt][0], acc[mt][nt][0]);
                    runmax[mt][1] = fmaxf(runmax[mt][1], acc[mt][nt][2]);
                }
                if (c0+1 < Lp-1){
                    runmax[mt][0] = fmaxf(runmax[mt][0], acc[mt][nt][1]);
                    runmax[mt][1] = fmaxf(runmax[mt][1], acc[mt][nt][3]);
                }
            }
        }
    }

    /* reduce across the 4 lanes sharing a row */
    #pragma unroll
    for (int mt=0;mt<2;mt++){
        #pragma unroll
        for (int h=0;h<2;h++){
            runmax[mt][h] = fmaxf(runmax[mt][h], __shfl_xor_sync(0xffffffffu, runmax[mt][h], 1));
            runmax[mt][h] = fmaxf(runmax[mt][h], __shfl_xor_sync(0xffffffffu, runmax[mt][h], 2));
        }
    }
    if ((lane&3)==0){
        #pragma unroll
        for (int mt=0;mt<2;mt++){
            int row = wm*32 + mt*16 + (lane>>2);
            red[row][wn]   = runmax[mt][0];
            red[row+8][wn] = runmax[mt][1];
        }
    }
    __syncthreads();
    if (tid < 128){
        int qr = qtile*128 + tid;
        if (qr < MQ){
            float v = fmaxf(red[tid][0], red[tid][1]);
            qmax[qr*Bp + pb] = v;
        }
    }
}

/* ---------------- dense: CLS cosine / TEMP ---------------- */
__global__ void dense_kernel(const float* __restrict__ qh, const float* __restrict__ ph,
                             float* __restrict__ out)
{
    int pb = blockIdx.x, qb = blockIdx.y, tid = threadIdx.x;
    const float* q = qh + (size_t)qb*Lq*Hd;
    const float* p = ph + (size_t)pb*Lp*Hd;
    float qq=0.f, pp=0.f, qp=0.f;
    for (int i=tid;i<Hd;i+=256){ float a=q[i], b=p[i];
        qq=fmaf(a,a,qq); pp=fmaf(b,b,pp); qp=fmaf(a,b,qp); }
    __shared__ float r0[256], r1[256], r2[256];
    r0[tid]=qq; r1[tid]=pp; r2[tid]=qp; __syncthreads();
    for (int o=128;o>0;o>>=1){
        if (tid<o){ r0[tid]+=r0[tid+o]; r1[tid]+=r1[tid+o]; r2[tid]+=r2[tid+o]; }
        __syncthreads();
    }
    if (tid==0){
        float d = fmaxf(sqrtf(r0[0]),1e-12f)*fmaxf(sqrtf(r1[0]),1e-12f);
        out[qb*Bp+pb] = r2[0]/d*INV_TEMP;
    }
}

/* ---------------- sparse ---------------- */
__global__ void tw_kernel(const float* __restrict__ hidden, const float* __restrict__ sw,
                          const float* __restrict__ sbp, float* __restrict__ tw, int total)
{
    int w = (blockIdx.x*blockDim.x + threadIdx.x) >> 5;
    int lane = threadIdx.x & 31;
    if (w >= total) return;
    const float* h = hidden + (size_t)w*Hd;
    float s = 0.f;
    for (int i=lane;i<Hd;i+=32) s = fmaf(h[i], sw[i], s);
    #pragma unroll
    for (int o=16;o;o>>=1) s += __shfl_xor_sync(0xffffffffu, s, o);
    if (lane==0) tw[w] = fmaxf(s + sbp[0], 0.f);
}

__global__ void canon_kernel(const int* __restrict__ ids, const float* __restrict__ tw,
                             float* __restrict__ weff, int L)
{
    __shared__ int   sid[512];
    __shared__ float stw[512];
    int b = blockIdx.x, i = threadIdx.x;
    int base = b*L;
    sid[i] = ids[base+i]; stw[i] = tw[base+i];
    __syncthreads();
    float w = stw[i]; int id = sid[i];
    if (id < 4) w = 0.f;
    else {
        for (int j=0;j<L;j++){
            if (j!=i && sid[j]==id){
                float wj = stw[j];
                if (wj > w || (wj==w && j<i)) { w=0.f; break; }
            }
        }
    }
    weff[base+i] = w;
}

__global__ void sparse_score_kernel(const int* __restrict__ q_ids, const float* __restrict__ wq,
                                    const int* __restrict__ p_ids, const float* __restrict__ wp,
                                    float* __restrict__ out)
{
    __shared__ int   spid[Lp];
    __shared__ float spw[Lp];
    __shared__ float red[256];
    int pb=blockIdx.x, qb=blockIdx.y, tid=threadIdx.x;
    for (int j=tid;j<Lp;j+=256){ spid[j]=p_ids[pb*Lp+j]; spw[j]=wp[pb*Lp+j]; }
    __syncthreads();
    float s = 0.f;
    if (tid < Lq){
        int id = q_ids[qb*Lq+tid]; float w = wq[qb*Lq+tid];
        if (w > 0.f){
            for (int j=0;j<Lp;j++) if (spid[j]==id) s = fmaf(w, spw[j], s);
        }
    }
    red[tid]=s; __syncthreads();
    for (int o=128;o>0;o>>=1){ if (tid<o) red[tid]+=red[tid+o]; __syncthreads(); }
    if (tid==0) out[Bq*Bp + qb*Bp+pb] = red[0]*INV_TEMP;
}

/* ---------------- bias + mask + L2-normalize, write bf16 ---------------- */
__global__ void bias_mask_norm_bf16(const float* __restrict__ C, const float* __restrict__ bias,
                                    const float* __restrict__ mask, __nv_bfloat16* __restrict__ out, int L)
{
    int row = blockIdx.x, tid = threadIdx.x;   /* 256 threads, 1024 cols */
    const float* c = C + (size_t)row*Hd;
    int Lm1 = L-1;
    float m = mask[(row/Lm1)*L + (row%Lm1) + 1];
    float4 v = *(const float4*)(c + tid*4);
    float4 bv = *(const float4*)(bias + tid*4);
    v.x=(v.x+bv.x)*m; v.y=(v.y+bv.y)*m; v.z=(v.z+bv.z)*m; v.w=(v.w+bv.w)*m;
    float ss = fmaf(v.x,v.x, fmaf(v.y,v.y, fmaf(v.z,v.z, v.w*v.w)));
    __shared__ float red[256];
    red[tid]=ss; __syncthreads();
    for (int o=128;o>0;o>>=1){ if (tid<o) red[tid]+=red[tid+o]; __syncthreads(); }
    float inv = 1.0f / fmaxf(sqrtf(red[0]), 1e-12f);
    __nv_bfloat162 lo = __floats2bfloat162_rn(v.x*inv, v.y*inv);
    __nv_bfloat162 hi = __floats2bfloat162_rn(v.z*inv, v.w*inv);
    uint2 o2; o2.x = *(unsigned*)&lo; o2.y = *(unsigned*)&hi;
    *(uint2*)(out + (size_t)row*Hd + tid*4) = o2;
}

__global__ void colbert_final_kernel(const float* __restrict__ qmax,
                                     const float* __restrict__ q_mask,
                                     float* __restrict__ out)
{
    int pb=blockIdx.x, qb=blockIdx.y, tid=threadIdx.x;  /* 128 threads */
    float v=0.f, mm=0.f;
    if (tid < Lq-1){
        v  = qmax[(qb*(Lq-1)+tid)*Bp + pb];
        mm = q_mask[qb*Lq + tid + 1];
    }
    __shared__ float rv[128], rm[128];
    rv[tid]=v; rm[tid]=mm; __syncthreads();
    for (int o=64;o>0;o>>=1){ if (tid<o){ rv[tid]+=rv[tid+o]; rm[tid]+=rm[tid+o]; } __syncthreads(); }
    if (tid==0) out[2*Bq*Bp + qb*Bp+pb] = rv[0]/rm[0]*INV_TEMP;
}

/* ---------------- launcher ---------------- */
extern "C" void kernel_launch(void* const* d_in, const int* in_sizes, int n_in,
                              void* d_out, int out_size)
{
    const float* q_hidden  = (const float*)d_in[0];
    const float* p_hidden  = (const float*)d_in[1];
    const float* q_mask    = (const float*)d_in[2];
    const float* p_mask    = (const float*)d_in[3];
    const int*   q_ids     = (const int*)  d_in[4];
    const int*   p_ids     = (const int*)  d_in[5];
    const float* colbert_w = (const float*)d_in[6];
    const float* colbert_b = (const float*)d_in[7];
    const float* sparse_w  = (const float*)d_in[8];
    const float* sparse_b  = (const float*)d_in[9];
    float* out = (float*)d_out;

    static float *p_tw_q=nullptr,*p_wq=nullptr,*p_tw_p=nullptr,*p_wp=nullptr,
                 *p_Qc=nullptr,*p_Pc=nullptr,*p_qmax=nullptr;
    static __nv_bfloat16 *p_qh=nullptr,*p_ph=nullptr,*p_w=nullptr,*p_Qcb=nullptr,*p_Pcb=nullptr;
    if (!p_tw_q){
        cudaGetSymbolAddress((void**)&p_tw_q, g_tw_q);
        cudaGetSymbolAddress((void**)&p_wq,   g_wq);
        cudaGetSymbolAddress((void**)&p_tw_p, g_tw_p);
        cudaGetSymbolAddress((void**)&p_wp,   g_wp);
        cudaGetSymbolAddress((void**)&p_Qc,   g_Qc);
        cudaGetSymbolAddress((void**)&p_Pc,   g_Pc);
        cudaGetSymbolAddress((void**)&p_qmax, g_qmax);
        cudaGetSymbolAddress((void**)&p_qh,   g_qh_bf);
        cudaGetSymbolAddress((void**)&p_ph,   g_ph_bf);
        cudaGetSymbolAddress((void**)&p_w,    g_w_bf);
        cudaGetSymbolAddress((void**)&p_Qcb,  g_Qcb);
        cudaGetSymbolAddress((void**)&p_Pcb,  g_Pcb);
    }

    dim3 gQP(Bp, Bq);

    /* convert to bf16 */
    f2bf_kernel<<<(Bq*Lq*Hd/4 + 255)/256, 256>>>(q_hidden, p_qh, Bq*Lq*Hd/4);
    f2bf_kernel<<<(Bp*Lp*Hd/4 + 255)/256, 256>>>(p_hidden, p_ph, Bp*Lp*Hd/4);
    f2bf_kernel<<<(Hd*Hd/4 + 255)/256, 256>>>(colbert_w, p_w, Hd*Hd/4);

    /* dense */
    dense_kernel<<<gQP, 256>>>(q_hidden, p_hidden, out);

    /* sparse */
    tw_kernel<<<(Bq*Lq*32+255)/256, 256>>>(q_hidden, sparse_w, sparse_b, p_tw_q, Bq*Lq);
    tw_kernel<<<(Bp*Lp*32+255)/256, 256>>>(p_hidden, sparse_w, sparse_b, p_tw_p, Bp*Lp);
    canon_kernel<<<Bq, Lq>>>(q_ids, p_tw_q, p_wq, Lq);
    canon_kernel<<<Bp, Lp>>>(p_ids, p_tw_p, p_wp, Lp);
    sparse_score_kernel<<<gQP, 256>>>(q_ids, p_wq, p_ids, p_wp, out);

    /* colbert projections (tensor core, bf16) */
    proj_gemm<<<dim3(Hd/64, (MQ+127)/128), 256>>>(p_qh, p_w, p_Qc, MQ, Lq);
    proj_gemm<<<dim3(Hd/64, (MP+127)/128), 256>>>(p_ph, p_w, p_Pc, MP, Lp);
    bias_mask_norm_bf16<<<MQ, 256>>>(p_Qc, colbert_b, q_mask, p_Qcb, Lq);
    bias_mask_norm_bf16<<<MP, 256>>>(p_Pc, colbert_b, p_mask, p_Pcb, Lp);

    /* fused maxsim GEMM + reduction */
    maxsim_gemm<<<dim3(Bp, (MQ+127)/128), 256>>>(p_Qcb, p_Pcb, p_qmax);
    colbert_final_kernel<<<gQP, 128>>>(p_qmax, q_mask, out);
}

// round 4
// speedup vs baseline: 5.7067x; 1.5643x over previous
#include <cuda_runtime.h>
#include <cuda_bf16.h>
#include <math.h>
#include <stdint.h>

#define Bq 8
#define Lq 128
#define Bp 64
#define Lp 512
#define Hd 1024
#define MQ (Bq*(Lq-1))   /* 1016  */
#define MP (Bp*(Lp-1))   /* 32704 */
#define INV_TEMP 50.0f

/* GEMM config: block 128x128, K-stage 64, 8 warps (4M x 2N), warp tile 32x64 */
#define KS   64
#define NSTG (Hd/KS)          /* 16 */
#define SAE  72               /* smem row stride in bf16 elems */
#define ROWB (SAE*2)          /* 144 bytes, 16B-aligned, ldmatrix conflict-free */
#define TILEB (128*ROWB)      /* one operand tile: 18432 B */
#define STGB  (2*TILEB)       /* A+B per stage: 36864 B */
#define RED_OFF (2*STGB)      /* reduction scratch after 2 stages */
#define SMEM_TOTAL (RED_OFF + 128*2*4)   /* 74752 B */

/* ---------------- scratch (allocation-free: device globals) ---------------- */
__device__ float g_tw_q[Bq*Lq];
__device__ float g_wq[Bq*Lq];
__device__ float g_tw_p[Bp*Lp];
__device__ float g_wp[Bp*Lp];
__device__ float g_Qc[(size_t)MQ*Hd];
__device__ float g_Pc[(size_t)MP*Hd];
__device__ float g_qmax[MQ*Bp];
__device__ __align__(256) __nv_bfloat16 g_qh_bf[(size_t)Bq*Lq*Hd];
__device__ __align__(256) __nv_bfloat16 g_ph_bf[(size_t)Bp*Lp*Hd];
__device__ __align__(256) __nv_bfloat16 g_w_bf[(size_t)Hd*Hd];
__device__ __align__(256) __nv_bfloat16 g_Qcb[(size_t)MQ*Hd];
__device__ __align__(256) __nv_bfloat16 g_Pcb[(size_t)MP*Hd];

/* ---------------- mma / cp.async helpers ---------------- */
__device__ __forceinline__ void mma_bf16(float* c, const unsigned* a, const unsigned* b){
    asm volatile("mma.sync.aligned.m16n8k16.row.col.f32.bf16.bf16.f32 "
        "{%0,%1,%2,%3}, {%4,%5,%6,%7}, {%8,%9}, {%0,%1,%2,%3};"
        : "+f"(c[0]), "+f"(c[1]), "+f"(c[2]), "+f"(c[3])
        : "r"(a[0]), "r"(a[1]), "r"(a[2]), "r"(a[3]), "r"(b[0]), "r"(b[1]));
}
__device__ __forceinline__ void ldm_x4(unsigned& r0, unsigned& r1, unsigned& r2, unsigned& r3, unsigned addr){
    asm volatile("ldmatrix.sync.aligned.m8n8.x4.shared.b16 {%0,%1,%2,%3}, [%4];"
        : "=r"(r0), "=r"(r1), "=r"(r2), "=r"(r3) : "r"(addr));
}
__device__ __forceinline__ void cpa16(unsigned dst, const void* src, unsigned sz){
    asm volatile("cp.async.cg.shared.global [%0], [%1], 16, %2;" :: "r"(dst), "l"(src), "r"(sz));
}
#define CP_COMMIT() asm volatile("cp.async.commit_group;" ::: "memory")
#define CP_WAIT1()  asm volatile("cp.async.wait_group 1;" ::: "memory")
#define CP_WAIT0()  asm volatile("cp.async.wait_group 0;" ::: "memory")

/* compute 4 k-steps (K=64 stage) for warp tile 32x64 */
__device__ __forceinline__ void mma_stage64(unsigned abase, unsigned bbase,
                                            int lane, int wm, int wn, float acc[2][8][4])
{
    #pragma unroll
    for (int k=0;k<4;k++){
        int klo = k*16;
        unsigned a[2][4];
        int m_i = lane>>3;
        int arow = ((m_i&1)<<3) + (lane&7);
        int acol = klo + ((m_i>>1)<<3);
        #pragma unroll
        for (int mt=0; mt<2; mt++){
            unsigned addr = abase + (unsigned)((wm*32 + mt*16 + arow)*ROWB + acol*2);
            ldm_x4(a[mt][0], a[mt][1], a[mt][2], a[mt][3], addr);
        }
        unsigned b[4][4];
        int brow = (lane&7) + ((lane>>4)<<3);
        int bcol = klo + (((lane>>3)&1)<<3);
        #pragma unroll
        for (int bpi=0; bpi<4; bpi++){
            unsigned addr = bbase + (unsigned)((wn*64 + bpi*16 + brow)*ROWB + bcol*2);
            ldm_x4(b[bpi][0], b[bpi][1], b[bpi][2], b[bpi][3], addr);
        }
        #pragma unroll
        for (int mt=0; mt<2; mt++)
            #pragma unroll
            for (int nt=0; nt<8; nt++)
                mma_bf16(acc[mt][nt], a[mt], &b[nt>>1][(nt&1)*2]);
    }
}

/* ---------------- projection GEMM: C[M,1024] = gather(A)[M,1024] * W^T ---------------- */
__global__ void __launch_bounds__(256)
proj_mma(const __nv_bfloat16* __restrict__ A, const __nv_bfloat16* __restrict__ W,
         float* __restrict__ C, int M, int La)
{
    extern __shared__ char smem[];
    unsigned sb = (unsigned)__cvta_generic_to_shared(smem);
    int tid = threadIdx.x, lane = tid&31, wid = tid>>5;
    int wm = wid>>1, wn = wid&1;
    int blkM = blockIdx.y*128, blkN = blockIdx.x*128;

    /* loader mappings: 4 A + 4 B 16B-transfers per thread per stage */
    const __nv_bfloat16* ap[4]; unsigned aofs[4]; unsigned asz[4];
    const __nv_bfloat16* bp[4]; unsigned bofs[4];
    int Lm1 = La - 1;
    #pragma unroll
    for (int i=0;i<4;i++){
        int id = tid + i*256, r = id>>3, c = id&7;
        int gr = blkM + r;
        asz[i] = (gr < M) ? 16u : 0u;
        long srow = (gr < M) ? ((long)(gr/Lm1)*La + gr%Lm1 + 1) : 0;
        ap[i] = A + srow*(long)Hd + c*8;
        aofs[i] = (unsigned)(r*ROWB + c*16);
        bp[i] = W + ((long)(blkN + r))*Hd + c*8;
        bofs[i] = (unsigned)(TILEB + r*ROWB + c*16);
    }

    float acc[2][8][4];
    #pragma unroll
    for (int mt=0;mt<2;mt++) for (int nt=0;nt<8;nt++) for (int j=0;j<4;j++) acc[mt][nt][j]=0.f;

    /* prefill stage 0 */
    #pragma unroll
    for (int i=0;i<4;i++){ cpa16(sb + aofs[i], ap[i], asz[i]); cpa16(sb + bofs[i], bp[i], 16u); }
    CP_COMMIT();

    #pragma unroll 1
    for (int s=0; s<NSTG; s++){
        if (s+1 < NSTG){
            unsigned nsb = sb + ((s+1)&1)*STGB;
            int k0 = (s+1)*KS;
            #pragma unroll
            for (int i=0;i<4;i++){
                cpa16(nsb + aofs[i], ap[i] + k0, asz[i]);
                cpa16(nsb + bofs[i], bp[i] + k0, 16u);
            }
            CP_COMMIT();
            CP_WAIT1();
        } else {
            CP_WAIT0();
        }
        __syncthreads();
        unsigned cs = sb + (s&1)*STGB;
        mma_stage64(cs, cs + TILEB, lane, wm, wn, acc);
        __syncthreads();
    }

    /* epilogue: fp32 store */
    #pragma unroll
    for (int mt=0;mt<2;mt++){
        int gr = blkM + wm*32 + mt*16 + (lane>>2);
        #pragma unroll
        for (int nt=0;nt<8;nt++){
            int gc = blkN + wn*64 + nt*8 + 2*(lane&3);
            if (gr < M)   *(float2*)(C + (size_t)gr*Hd + gc)     = make_float2(acc[mt][nt][0], acc[mt][nt][1]);
            if (gr+8 < M) *(float2*)(C + (size_t)(gr+8)*Hd + gc) = make_float2(acc[mt][nt][2], acc[mt][nt][3]);
        }
    }
}

/* ---------------- fused maxsim GEMM: running row-max over passage tokens ---------------- */
__global__ void __launch_bounds__(256)
maxsim_mma(const __nv_bfloat16* __restrict__ Qcb, const __nv_bfloat16* __restrict__ Pcb,
           float* __restrict__ qmax)
{
    extern __shared__ char smem[];
    unsigned sb = (unsigned)__cvta_generic_to_shared(smem);
    float* red = (float*)(smem + RED_OFF);
    int tid = threadIdx.x, lane = tid&31, wid = tid>>5;
    int wm = wid>>1, wn = wid&1;
    int pb = blockIdx.x, qtile = blockIdx.y;
    int blkM = qtile*128;

    const __nv_bfloat16* ap[4]; unsigned aofs[4]; unsigned asz[4];
    const __nv_bfloat16* bp[4]; unsigned bofs[4]; int brr[4];
    const __nv_bfloat16* Pbase = Pcb + (size_t)pb*(Lp-1)*Hd;
    #pragma unroll
    for (int i=0;i<4;i++){
        int id = tid + i*256, r = id>>3, c = id&7;
        int gr = blkM + r;
        asz[i] = (gr < MQ) ? 16u : 0u;
        ap[i] = Qcb + ((size_t)(gr < MQ ? gr : 0))*Hd + c*8;
        aofs[i] = (unsigned)(r*ROWB + c*16);
        brr[i] = r;
        bp[i] = Pbase + (size_t)r*Hd + c*8;
        bofs[i] = (unsigned)(TILEB + r*ROWB + c*16);
    }

    float runmax[2][2];
    runmax[0][0]=runmax[0][1]=runmax[1][0]=runmax[1][1]=-1e30f;

    #pragma unroll 1
    for (int nc=0; nc<4; nc++){
        const long bsh = (long)nc*128*Hd;
        unsigned bsz[4];
        #pragma unroll
        for (int i=0;i<4;i++) bsz[i] = (nc*128 + brr[i] < Lp-1) ? 16u : 0u;

        float acc[2][8][4];
        #pragma unroll
        for (int mt=0;mt<2;mt++) for (int nt=0;nt<8;nt++) for (int j=0;j<4;j++) acc[mt][nt][j]=0.f;

        #pragma unroll
        for (int i=0;i<4;i++){ cpa16(sb + aofs[i], ap[i], asz[i]); cpa16(sb + bofs[i], bp[i] + bsh, bsz[i]); }
        CP_COMMIT();

        #pragma unroll 1
        for (int s=0; s<NSTG; s++){
            if (s+1 < NSTG){
                unsigned nsb = sb + ((s+1)&1)*STGB;
                int k0 = (s+1)*KS;
                #pragma unroll
                for (int i=0;i<4;i++){
                    cpa16(nsb + aofs[i], ap[i] + k0, asz[i]);
                    cpa16(nsb + bofs[i], bp[i] + bsh + k0, bsz[i]);
                }
                CP_COMMIT();
                CP_WAIT1();
            } else {
                CP_WAIT0();
            }
            __syncthreads();
            unsigned cs = sb + (s&1)*STGB;
            mma_stage64(cs, cs + TILEB, lane, wm, wn, acc);
            __syncthreads();
        }

        /* fold into running max with column mask */
        #pragma unroll
        for (int mt=0;mt<2;mt++){
            #pragma unroll
            for (int nt=0;nt<8;nt++){
                int c0 = nc*128 + wn*64 + nt*8 + 2*(lane&3);
                if (c0 < Lp-1){
                    runmax[mt][0] = fmaxf(runmax[mt][0], acc[mt][nt][0]);
                    runmax[mt][1] = fmaxf(runmax[mt][1], acc[mt][nt][2]);
                }
                if (c0+1 < Lp-1){
                    runmax[mt][0] = fmaxf(runmax[mt][0], acc[mt][nt][1]);
                    runmax[mt][1] = fmaxf(runmax[mt][1], acc[mt][nt][3]);
                }
            }
        }
    }

    /* reduce across the 4 lanes sharing a row, then across the 2 n-warps */
    #pragma unroll
    for (int mt=0;mt<2;mt++){
        #pragma unroll
        for (int h=0;h<2;h++){
            runmax[mt][h] = fmaxf(runmax[mt][h], __shfl_xor_sync(0xffffffffu, runmax[mt][h], 1));
            runmax[mt][h] = fmaxf(runmax[mt][h], __shfl_xor_sync(0xffffffffu, runmax[mt][h], 2));
        }
    }
    if ((lane&3)==0){
        #pragma unroll
        for (int mt=0;mt<2;mt++){
            int row = wm*32 + mt*16 + (lane>>2);
            red[row*2 + wn]     = runmax[mt][0];
            red[(row+8)*2 + wn] = runmax[mt][1];
        }
    }
    __syncthreads();
    if (tid < 128){
        int gr = blkM + tid;
        if (gr < MQ) qmax[gr*Bp + pb] = fmaxf(red[tid*2], red[tid*2+1]);
    }
}

/* ---------------- f32 -> bf16 convert ---------------- */
__global__ void f2bf_kernel(const float* __restrict__ in, __nv_bfloat16* __restrict__ out, int n4){
    int i = blockIdx.x*blockDim.x + threadIdx.x;
    if (i < n4){
        float4 v = *(const float4*)(in + (size_t)i*4);
        __nv_bfloat162 lo = __floats2bfloat162_rn(v.x, v.y);
        __nv_bfloat162 hi = __floats2bfloat162_rn(v.z, v.w);
        uint2 o; o.x = *(unsigned*)&lo; o.y = *(unsigned*)&hi;
        *(uint2*)(out + (size_t)i*4) = o;
    }
}

/* ---------------- dense: CLS cosine / TEMP ---------------- */
__global__ void dense_kernel(const float* __restrict__ qh, const float* __restrict__ ph,
                             float* __restrict__ out)
{
    int pb = blockIdx.x, qb = blockIdx.y, tid = threadIdx.x;
    const float* q = qh + (size_t)qb*Lq*Hd;
    const float* p = ph + (size_t)pb*Lp*Hd;
    float qq=0.f, pp=0.f, qp=0.f;
    for (int i=tid;i<Hd;i+=256){ float a=q[i], b=p[i];
        qq=fmaf(a,a,qq); pp=fmaf(b,b,pp); qp=fmaf(a,b,qp); }
    __shared__ float r0[256], r1[256], r2[256];
    r0[tid]=qq; r1[tid]=pp; r2[tid]=qp; __syncthreads();
    for (int o=128;o>0;o>>=1){
        if (tid<o){ r0[tid]+=r0[tid+o]; r1[tid]+=r1[tid+o]; r2[tid]+=r2[tid+o]; }
        __syncthreads();
    }
    if (tid==0){
        float d = fmaxf(sqrtf(r0[0]),1e-12f)*fmaxf(sqrtf(r1[0]),1e-12f);
        out[qb*Bp+pb] = r2[0]/d*INV_TEMP;
    }
}

/* ---------------- sparse ---------------- */
__global__ void tw_kernel(const float* __restrict__ hidden, const float* __restrict__ sw,
                          const float* __restrict__ sbp, float* __restrict__ tw, int total)
{
    int w = (blockIdx.x*blockDim.x + threadIdx.x) >> 5;
    int lane = threadIdx.x & 31;
    if (w >= total) return;
    const float* h = hidden + (size_t)w*Hd;
    float s = 0.f;
    for (int i=lane;i<Hd;i+=32) s = fmaf(h[i], sw[i], s);
    #pragma unroll
    for (int o=16;o;o>>=1) s += __shfl_xor_sync(0xffffffffu, s, o);
    if (lane==0) tw[w] = fmaxf(s + sbp[0], 0.f);
}

__global__ void canon_kernel(const int* __restrict__ ids, const float* __restrict__ tw,
                             float* __restrict__ weff, int L)
{
    __shared__ int   sid[512];
    __shared__ float stw[512];
    int b = blockIdx.x, i = threadIdx.x;
    int base = b*L;
    sid[i] = ids[base+i]; stw[i] = tw[base+i];
    __syncthreads();
    float w = stw[i]; int id = sid[i];
    if (id < 4) w = 0.f;
    else {
        for (int j=0;j<L;j++){
            if (j!=i && sid[j]==id){
                float wj = stw[j];
                if (wj > w || (wj==w && j<i)) { w=0.f; break; }
            }
        }
    }
    weff[base+i] = w;
}

__global__ void sparse_score_kernel(const int* __restrict__ q_ids, const float* __restrict__ wq,
                                    const int* __restrict__ p_ids, const float* __restrict__ wp,
                                    float* __restrict__ out)
{
    __shared__ int   spid[Lp];
    __shared__ float spw[Lp];
    __shared__ float red[256];
    int pb=blockIdx.x, qb=blockIdx.y, tid=threadIdx.x;
    for (int j=tid;j<Lp;j+=256){ spid[j]=p_ids[pb*Lp+j]; spw[j]=wp[pb*Lp+j]; }
    __syncthreads();
    float s = 0.f;
    if (tid < Lq){
        int id = q_ids[qb*Lq+tid]; float w = wq[qb*Lq+tid];
        if (w > 0.f){
            for (int j=0;j<Lp;j++) if (spid[j]==id) s = fmaf(w, spw[j], s);
        }
    }
    red[tid]=s; __syncthreads();
    for (int o=128;o>0;o>>=1){ if (tid<o) red[tid]+=red[tid+o]; __syncthreads(); }
    if (tid==0) out[Bq*Bp + qb*Bp+pb] = red[0]*INV_TEMP;
}

/* ---------------- bias + mask + L2-normalize, write bf16 ---------------- */
__global__ void bias_mask_norm_bf16(const float* __restrict__ C, const float* __restrict__ bias,
                                    const float* __restrict__ mask, __nv_bfloat16* __restrict__ out, int L)
{
    int row = blockIdx.x, tid = threadIdx.x;   /* 256 threads, 1024 cols */
    const float* c = C + (size_t)row*Hd;
    int Lm1 = L-1;
    float m = mask[(row/Lm1)*L + (row%Lm1) + 1];
    float4 v = *(const float4*)(c + tid*4);
    float4 bv = *(const float4*)(bias + tid*4);
    v.x=(v.x+bv.x)*m; v.y=(v.y+bv.y)*m; v.z=(v.z+bv.z)*m; v.w=(v.w+bv.w)*m;
    float ss = fmaf(v.x,v.x, fmaf(v.y,v.y, fmaf(v.z,v.z, v.w*v.w)));
    __shared__ float red[256];
    red[tid]=ss; __syncthreads();
    for (int o=128;o>0;o>>=1){ if (tid<o) red[tid]+=red[tid+o]; __syncthreads(); }
    float inv = 1.0f / fmaxf(sqrtf(red[0]), 1e-12f);
    __nv_bfloat162 lo = __floats2bfloat162_rn(v.x*inv, v.y*inv);
    __nv_bfloat162 hi = __floats2bfloat162_rn(v.z*inv, v.w*inv);
    uint2 o2; o2.x = *(unsigned*)&lo; o2.y = *(unsigned*)&hi;
    *(uint2*)(out + (size_t)row*Hd + tid*4) = o2;
}

__global__ void colbert_final_kernel(const float* __restrict__ qmax,
                                     const float* __restrict__ q_mask,
                                     float* __restrict__ out)
{
    int pb=blockIdx.x, qb=blockIdx.y, tid=threadIdx.x;  /* 128 threads */
    float v=0.f, mm=0.f;
    if (tid < Lq-1){
        v  = qmax[(qb*(Lq-1)+tid)*Bp + pb];
        mm = q_mask[qb*Lq + tid + 1];
    }
    __shared__ float rv[128], rm[128];
    rv[tid]=v; rm[tid]=mm; __syncthreads();
    for (int o=64;o>0;o>>=1){ if (tid<o){ rv[tid]+=rv[tid+o]; rm[tid]+=rm[tid+o]; } __syncthreads(); }
    if (tid==0) out[2*Bq*Bp + qb*Bp+pb] = rv[0]/rm[0]*INV_TEMP;
}

/* ---------------- launcher ---------------- */
extern "C" void kernel_launch(void* const* d_in, const int* in_sizes, int n_in,
                              void* d_out, int out_size)
{
    const float* q_hidden  = (const float*)d_in[0];
    const float* p_hidden  = (const float*)d_in[1];
    const float* q_mask    = (const float*)d_in[2];
    const float* p_mask    = (const float*)d_in[3];
    const int*   q_ids     = (const int*)  d_in[4];
    const int*   p_ids     = (const int*)  d_in[5];
    const float* colbert_w = (const float*)d_in[6];
    const float* colbert_b = (const float*)d_in[7];
    const float* sparse_w  = (const float*)d_in[8];
    const float* sparse_b  = (const float*)d_in[9];
    float* out = (float*)d_out;

    static float *p_tw_q=nullptr,*p_wq=nullptr,*p_tw_p=nullptr,*p_wp=nullptr,
                 *p_Qc=nullptr,*p_Pc=nullptr,*p_qmax=nullptr;
    static __nv_bfloat16 *p_qh=nullptr,*p_ph=nullptr,*p_w=nullptr,*p_Qcb=nullptr,*p_Pcb=nullptr;
    if (!p_tw_q){
        cudaGetSymbolAddress((void**)&p_tw_q, g_tw_q);
        cudaGetSymbolAddress((void**)&p_wq,   g_wq);
        cudaGetSymbolAddress((void**)&p_tw_p, g_tw_p);
        cudaGetSymbolAddress((void**)&p_wp,   g_wp);
        cudaGetSymbolAddress((void**)&p_Qc,   g_Qc);
        cudaGetSymbolAddress((void**)&p_Pc,   g_Pc);
        cudaGetSymbolAddress((void**)&p_qmax, g_qmax);
        cudaGetSymbolAddress((void**)&p_qh,   g_qh_bf);
        cudaGetSymbolAddress((void**)&p_ph,   g_ph_bf);
        cudaGetSymbolAddress((void**)&p_w,    g_w_bf);
        cudaGetSymbolAddress((void**)&p_Qcb,  g_Qcb);
        cudaGetSymbolAddress((void**)&p_Pcb,  g_Pcb);
        cudaFuncSetAttribute(proj_mma,   cudaFuncAttributeMaxDynamicSharedMemorySize, SMEM_TOTAL);
        cudaFuncSetAttribute(maxsim_mma, cudaFuncAttributeMaxDynamicSharedMemorySize, SMEM_TOTAL);
    }

    dim3 gQP(Bp, Bq);

    /* convert to bf16 */
    f2bf_kernel<<<(Bq*Lq*Hd/4 + 255)/256, 256>>>(q_hidden, p_qh, Bq*Lq*Hd/4);
    f2bf_kernel<<<(Bp*Lp*Hd/4 + 255)/256, 256>>>(p_hidden, p_ph, Bp*Lp*Hd/4);
    f2bf_kernel<<<(Hd*Hd/4 + 255)/256, 256>>>(colbert_w, p_w, Hd*Hd/4);

    /* dense */
    dense_kernel<<<gQP, 256>>>(q_hidden, p_hidden, out);

    /* sparse */
    tw_kernel<<<(Bq*Lq*32+255)/256, 256>>>(q_hidden, sparse_w, sparse_b, p_tw_q, Bq*Lq);
    tw_kernel<<<(Bp*Lp*32+255)/256, 256>>>(p_hidden, sparse_w, sparse_b, p_tw_p, Bp*Lp);
    canon_kernel<<<Bq, Lq>>>(q_ids, p_tw_q, p_wq, Lq);
    canon_kernel<<<Bp, Lp>>>(p_ids, p_tw_p, p_wp, Lp);
    sparse_score_kernel<<<gQP, 256>>>(q_ids, p_wq, p_ids, p_wp, out);

    /* colbert projections (HMMA, cp.async pipelined) */
    proj_mma<<<dim3(Hd/128, (MQ+127)/128), 256, SMEM_TOTAL>>>(p_qh, p_w, p_Qc, MQ, Lq);
    proj_mma<<<dim3(Hd/128, (MP+127)/128), 256, SMEM_TOTAL>>>(p_ph, p_w, p_Pc, MP, Lp);
    bias_mask_norm_bf16<<<MQ, 256>>>(p_Qc, colbert_b, q_mask, p_Qcb, Lq);
    bias_mask_norm_bf16<<<MP, 256>>>(p_Pc, colbert_b, p_mask, p_Pcb, Lp);

    /* fused maxsim GEMM + reduction */
    maxsim_mma<<<dim3(Bp, (MQ+127)/128), 256, SMEM_TOTAL>>>(p_Qcb, p_Pcb, p_qmax);
    colbert_final_kernel<<<gQP, 128>>>(p_qmax, q_mask, out);
}

// round 5
// speedup vs baseline: 6.2906x; 1.1023x over previous
#include <cuda_runtime.h>
#include <cuda_bf16.h>
#include <math.h>
#include <stdint.h>

#define Bq 8
#define Lq 128
#define Bp 64
#define Lp 512
#define Hd 1024
#define MQ (Bq*(Lq-1))   /* 1016  */
#define MP (Bp*(Lp-1))   /* 32704 */
#define INV_TEMP 50.0f

/* GEMM config: block 128x128, K-stage 64, 8 warps (4M x 2N), warp tile 32x64 */
#define KS   64
#define NSTG (Hd/KS)          /* 16 */
#define SAE  72               /* smem row stride in bf16 elems */
#define ROWB (SAE*2)          /* 144 bytes */
#define TILEB (128*ROWB)      /* 18432 B */
#define STGB  (2*TILEB)       /* 36864 B */
#define RED_OFF (2*STGB)
#define SMEM_TOTAL (RED_OFF + 128*2*4)   /* 74752 B */

/* ---------------- scratch (allocation-free: device globals) ---------------- */
__device__ float g_tw_q[Bq*Lq];
__device__ float g_wq[Bq*Lq];
__device__ float g_tw_p[Bp*Lp];
__device__ float g_wp[Bp*Lp];
__device__ float g_qmax[MQ*Bp];
__device__ float g_ssq_q[MQ*16];
__device__ float g_ssq_p[(size_t)MP*16];
__device__ __align__(256) __nv_bfloat16 g_qh_bf[(size_t)Bq*Lq*Hd];
__device__ __align__(256) __nv_bfloat16 g_ph_bf[(size_t)Bp*Lp*Hd];
__device__ __align__(256) __nv_bfloat16 g_w_bf[(size_t)Hd*Hd];
__device__ __align__(256) __nv_bfloat16 g_Qcb[(size_t)MQ*Hd];
__device__ __align__(256) __nv_bfloat16 g_Pcb[(size_t)MP*Hd];

/* ---------------- mma / cp.async helpers ---------------- */
__device__ __forceinline__ void mma_bf16(float* c, const unsigned* a, const unsigned* b){
    asm volatile("mma.sync.aligned.m16n8k16.row.col.f32.bf16.bf16.f32 "
        "{%0,%1,%2,%3}, {%4,%5,%6,%7}, {%8,%9}, {%0,%1,%2,%3};"
        : "+f"(c[0]), "+f"(c[1]), "+f"(c[2]), "+f"(c[3])
        : "r"(a[0]), "r"(a[1]), "r"(a[2]), "r"(a[3]), "r"(b[0]), "r"(b[1]));
}
__device__ __forceinline__ void ldm_x4(unsigned& r0, unsigned& r1, unsigned& r2, unsigned& r3, unsigned addr){
    asm volatile("ldmatrix.sync.aligned.m8n8.x4.shared.b16 {%0,%1,%2,%3}, [%4];"
        : "=r"(r0), "=r"(r1), "=r"(r2), "=r"(r3) : "r"(addr));
}
__device__ __forceinline__ void cpa16(unsigned dst, const void* src, unsigned sz){
    asm volatile("cp.async.cg.shared.global [%0], [%1], 16, %2;" :: "r"(dst), "l"(src), "r"(sz));
}
#define CP_COMMIT() asm volatile("cp.async.commit_group;" ::: "memory")
#define CP_WAIT1()  asm volatile("cp.async.wait_group 1;" ::: "memory")
#define CP_WAIT0()  asm volatile("cp.async.wait_group 0;" ::: "memory")

/* compute 4 k-steps (K=64 stage) for warp tile 32x64 */
__device__ __forceinline__ void mma_stage64(unsigned abase, unsigned bbase,
                                            int lane, int wm, int wn, float acc[2][8][4])
{
    #pragma unroll
    for (int k=0;k<4;k++){
        int klo = k*16;
        unsigned a[2][4];
        int m_i = lane>>3;
        int arow = ((m_i&1)<<3) + (lane&7);
        int acol = klo + ((m_i>>1)<<3);
        #pragma unroll
        for (int mt=0; mt<2; mt++){
            unsigned addr = abase + (unsigned)((wm*32 + mt*16 + arow)*ROWB + acol*2);
            ldm_x4(a[mt][0], a[mt][1], a[mt][2], a[mt][3], addr);
        }
        unsigned b[4][4];
        int brow = (lane&7) + ((lane>>4)<<3);
        int bcol = klo + (((lane>>3)&1)<<3);
        #pragma unroll
        for (int bpi=0; bpi<4; bpi++){
            unsigned addr = bbase + (unsigned)((wn*64 + bpi*16 + brow)*ROWB + bcol*2);
            ldm_x4(b[bpi][0], b[bpi][1], b[bpi][2], b[bpi][3], addr);
        }
        #pragma unroll
        for (int mt=0; mt<2; mt++)
            #pragma unroll
            for (int nt=0; nt<8; nt++)
                mma_bf16(acc[mt][nt], a[mt], &b[nt>>1][(nt&1)*2]);
    }
}

/* ---------------- projection GEMM + fused bias/mask epilogue, bf16 out ---------------- */
__global__ void __launch_bounds__(256,2)
proj_mma(const __nv_bfloat16* __restrict__ A, const __nv_bfloat16* __restrict__ W,
         __nv_bfloat16* __restrict__ Cb, float* __restrict__ ssq,
         const float* __restrict__ bias, const float* __restrict__ mask,
         int M, int La)
{
    extern __shared__ char smem[];
    unsigned sb = (unsigned)__cvta_generic_to_shared(smem);
    int tid = threadIdx.x, lane = tid&31, wid = tid>>5;
    int wm = wid>>1, wn = wid&1;
    int blkM = blockIdx.y*128, blkN = blockIdx.x*128;
    int Lm1 = La - 1;

    const __nv_bfloat16* ap[4]; unsigned aofs[4]; unsigned asz[4];
    const __nv_bfloat16* bp[4]; unsigned bofs[4];
    #pragma unroll
    for (int i=0;i<4;i++){
        int id = tid + i*256, r = id>>3, c = id&7;
        int gr = blkM + r;
        asz[i] = (gr < M) ? 16u : 0u;
        long srow = (gr < M) ? ((long)(gr/Lm1)*La + gr%Lm1 + 1) : 0;
        ap[i] = A + srow*(long)Hd + c*8;
        aofs[i] = (unsigned)(r*ROWB + c*16);
        bp[i] = W + ((long)(blkN + r))*Hd + c*8;
        bofs[i] = (unsigned)(TILEB + r*ROWB + c*16);
    }

    float acc[2][8][4];
    #pragma unroll
    for (int mt=0;mt<2;mt++) for (int nt=0;nt<8;nt++) for (int j=0;j<4;j++) acc[mt][nt][j]=0.f;

    #pragma unroll
    for (int i=0;i<4;i++){ cpa16(sb + aofs[i], ap[i], asz[i]); cpa16(sb + bofs[i], bp[i], 16u); }
    CP_COMMIT();

    #pragma unroll 1
    for (int s=0; s<NSTG; s++){
        if (s+1 < NSTG){
            unsigned nsb = sb + ((s+1)&1)*STGB;
            int k0 = (s+1)*KS;
            #pragma unroll
            for (int i=0;i<4;i++){
                cpa16(nsb + aofs[i], ap[i] + k0, asz[i]);
                cpa16(nsb + bofs[i], bp[i] + k0, 16u);
            }
            CP_COMMIT();
            CP_WAIT1();
        } else {
            CP_WAIT0();
        }
        __syncthreads();
        unsigned cs = sb + (s&1)*STGB;
        mma_stage64(cs, cs + TILEB, lane, wm, wn, acc);
        __syncthreads();
    }

    /* epilogue: bias + mask, partial sumsq, bf16 store */
    #pragma unroll
    for (int mt=0;mt<2;mt++){
        #pragma unroll
        for (int half=0; half<2; half++){
            int gr = blkM + wm*32 + mt*16 + (lane>>2) + half*8;
            bool valid = gr < M;
            float m = 0.f;
            if (valid) m = mask[(gr/Lm1)*La + gr%Lm1 + 1];
            float ss = 0.f;
            #pragma unroll
            for (int nt=0;nt<8;nt++){
                int gc = blkN + wn*64 + nt*8 + 2*(lane&3);
                float v0 = (acc[mt][nt][half*2+0] + bias[gc])   * m;
                float v1 = (acc[mt][nt][half*2+1] + bias[gc+1]) * m;
                ss = fmaf(v0,v0, fmaf(v1,v1, ss));
                if (valid){
                    __nv_bfloat162 bv = __floats2bfloat162_rn(v0, v1);
                    *(__nv_bfloat162*)(Cb + (size_t)gr*Hd + gc) = bv;
                }
            }
            ss += __shfl_xor_sync(0xffffffffu, ss, 1);
            ss += __shfl_xor_sync(0xffffffffu, ss, 2);
            if (valid && (lane&3)==0)
                ssq[(size_t)gr*16 + blockIdx.x*2 + wn] = ss;
        }
    }
}

/* ---------------- L2-norm scale in place (bf16) ---------------- */
__global__ void scale_norm(__nv_bfloat16* __restrict__ Cb, const float* __restrict__ ssq)
{
    int row = blockIdx.x, tid = threadIdx.x;   /* 128 threads */
    __shared__ float sinv;
    if (tid == 0){
        float ss = 0.f;
        #pragma unroll
        for (int i=0;i<16;i++) ss += ssq[(size_t)row*16 + i];
        sinv = 1.0f / fmaxf(sqrtf(ss), 1e-12f);
    }
    __syncthreads();
    float inv = sinv;
    uint4 v = *(uint4*)(Cb + (size_t)row*Hd + tid*8);
    __nv_bfloat162* pv = (__nv_bfloat162*)&v;
    #pragma unroll
    for (int j=0;j<4;j++){
        float2 f = __bfloat1622float2(pv[j]);
        pv[j] = __floats2bfloat162_rn(f.x*inv, f.y*inv);
    }
    *(uint4*)(Cb + (size_t)row*Hd + tid*8) = v;
}

/* ---------------- fused maxsim GEMM: running row-max over passage tokens ---------------- */
__global__ void __launch_bounds__(256,2)
maxsim_mma(const __nv_bfloat16* __restrict__ Qcb, const __nv_bfloat16* __restrict__ Pcb,
           float* __restrict__ qmax)
{
    extern __shared__ char smem[];
    unsigned sb = (unsigned)__cvta_generic_to_shared(smem);
    float* red = (float*)(smem + RED_OFF);
    int tid = threadIdx.x, lane = tid&31, wid = tid>>5;
    int wm = wid>>1, wn = wid&1;
    int pb = blockIdx.x, qtile = blockIdx.y;
    int blkM = qtile*128;

    const __nv_bfloat16* ap[4]; unsigned aofs[4]; unsigned asz[4];
    const __nv_bfloat16* bp[4]; unsigned bofs[4]; int brr[4];
    const __nv_bfloat16* Pbase = Pcb + (size_t)pb*(Lp-1)*Hd;
    #pragma unroll
    for (int i=0;i<4;i++){
        int id = tid + i*256, r = id>>3, c = id&7;
        int gr = blkM + r;
        asz[i] = (gr < MQ) ? 16u : 0u;
        ap[i] = Qcb + ((size_t)(gr < MQ ? gr : 0))*Hd + c*8;
        aofs[i] = (unsigned)(r*ROWB + c*16);
        brr[i] = r;
        bp[i] = Pbase + (size_t)r*Hd + c*8;
        bofs[i] = (unsigned)(TILEB + r*ROWB + c*16);
    }

    float runmax[2][2];
    runmax[0][0]=runmax[0][1]=runmax[1][0]=runmax[1][1]=-1e30f;

    #pragma unroll 1
    for (int nc=0; nc<4; nc++){
        const long bsh = (long)nc*128*Hd;
        unsigned bsz[4];
        #pragma unroll
        for (int i=0;i<4;i++) bsz[i] = (nc*128 + brr[i] < Lp-1) ? 16u : 0u;

        float acc[2][8][4];
        #pragma unroll
        for (int mt=0;mt<2;mt++) for (int nt=0;nt<8;nt++) for (int j=0;j<4;j++) acc[mt][nt][j]=0.f;

        #pragma unroll
        for (int i=0;i<4;i++){ cpa16(sb + aofs[i], ap[i], asz[i]); cpa16(sb + bofs[i], bp[i] + bsh, bsz[i]); }
        CP_COMMIT();

        #pragma unroll 1
        for (int s=0; s<NSTG; s++){
            if (s+1 < NSTG){
                unsigned nsb = sb + ((s+1)&1)*STGB;
                int k0 = (s+1)*KS;
                #pragma unroll
                for (int i=0;i<4;i++){
                    cpa16(nsb + aofs[i], ap[i] + k0, asz[i]);
                    cpa16(nsb + bofs[i], bp[i] + bsh + k0, bsz[i]);
                }
                CP_COMMIT();
                CP_WAIT1();
            } else {
                CP_WAIT0();
            }
            __syncthreads();
            unsigned cs = sb + (s&1)*STGB;
            mma_stage64(cs, cs + TILEB, lane, wm, wn, acc);
            __syncthreads();
        }

        #pragma unroll
        for (int mt=0;mt<2;mt++){
            #pragma unroll
            for (int nt=0;nt<8;nt++){
                int c0 = nc*128 + wn*64 + nt*8 + 2*(lane&3);
                if (c0 < Lp-1){
                    runmax[mt][0] = fmaxf(runmax[mt][0], acc[mt][nt][0]);
                    runmax[mt][1] = fmaxf(runmax[mt][1], acc[mt][nt][2]);
                }
                if (c0+1 < Lp-1){
                    runmax[mt][0] = fmaxf(runmax[mt][0], acc[mt][nt][1]);
                    runmax[mt][1] = fmaxf(runmax[mt][1], acc[mt][nt][3]);
                }
            }
        }
    }

    #pragma unroll
    for (int mt=0;mt<2;mt++){
        #pragma unroll
        for (int h=0;h<2;h++){
            runmax[mt][h] = fmaxf(runmax[mt][h], __shfl_xor_sync(0xffffffffu, runmax[mt][h], 1));
            runmax[mt][h] = fmaxf(runmax[mt][h], __shfl_xor_sync(0xffffffffu, runmax[mt][h], 2));
        }
    }
    if ((lane&3)==0){
        #pragma unroll
        for (int mt=0;mt<2;mt++){
            int row = wm*32 + mt*16 + (lane>>2);
            red[row*2 + wn]     = runmax[mt][0];
            red[(row+8)*2 + wn] = runmax[mt][1];
        }
    }
    __syncthreads();
    if (tid < 128){
        int gr = blkM + tid;
        if (gr < MQ) qmax[gr*Bp + pb] = fmaxf(red[tid*2], red[tid*2+1]);
    }
}

/* ---------------- fused f32->bf16 convert + sparse token weight ---------------- */
__global__ void cvt_tw_kernel(const float* __restrict__ hidden, const float* __restrict__ sw,
                              const float* __restrict__ sbp,
                              __nv_bfloat16* __restrict__ outbf, float* __restrict__ tw)
{
    int row = blockIdx.x, tid = threadIdx.x;   /* 128 threads, 8 f32 each */
    int lane = tid&31, wid = tid>>5;
    const float* h = hidden + (size_t)row*Hd + tid*8;
    float4 a = *(const float4*)h;
    float4 b = *(const float4*)(h+4);
    const float* w = sw + tid*8;
    float4 wa = *(const float4*)w;
    float4 wb = *(const float4*)(w+4);
    uint4 o;
    __nv_bfloat162 p0 = __floats2bfloat162_rn(a.x, a.y);
    __nv_bfloat162 p1 = __floats2bfloat162_rn(a.z, a.w);
    __nv_bfloat162 p2 = __floats2bfloat162_rn(b.x, b.y);
    __nv_bfloat162 p3 = __floats2bfloat162_rn(b.z, b.w);
    o.x = *(unsigned*)&p0; o.y = *(unsigned*)&p1; o.z = *(unsigned*)&p2; o.w = *(unsigned*)&p3;
    *(uint4*)(outbf + (size_t)row*Hd + tid*8) = o;
    float s = fmaf(a.x,wa.x, fmaf(a.y,wa.y, fmaf(a.z,wa.z, fmaf(a.w,wa.w,
              fmaf(b.x,wb.x, fmaf(b.y,wb.y, fmaf(b.z,wb.z, b.w*wb.w)))))));
    #pragma unroll
    for (int of=16;of;of>>=1) s += __shfl_xor_sync(0xffffffffu, s, of);
    __shared__ float ws[4];
    if (lane==0) ws[wid] = s;
    __syncthreads();
    if (tid==0) tw[row] = fmaxf(ws[0]+ws[1]+ws[2]+ws[3] + sbp[0], 0.f);
}

/* ---------------- f32 -> bf16 convert (weights only) ---------------- */
__global__ void f2bf_kernel(const float* __restrict__ in, __nv_bfloat16* __restrict__ out, int n4){
    int i = blockIdx.x*blockDim.x + threadIdx.x;
    if (i < n4){
        float4 v = *(const float4*)(in + (size_t)i*4);
        __nv_bfloat162 lo = __floats2bfloat162_rn(v.x, v.y);
        __nv_bfloat162 hi = __floats2bfloat162_rn(v.z, v.w);
        uint2 o; o.x = *(unsigned*)&lo; o.y = *(unsigned*)&hi;
        *(uint2*)(out + (size_t)i*4) = o;
    }
}

/* ---------------- dense: CLS cosine / TEMP ---------------- */
__global__ void dense_kernel(const float* __restrict__ qh, const float* __restrict__ ph,
                             float* __restrict__ out)
{
    int pb = blockIdx.x, qb = blockIdx.y, tid = threadIdx.x;
    const float* q = qh + (size_t)qb*Lq*Hd;
    const float* p = ph + (size_t)pb*Lp*Hd;
    float qq=0.f, pp=0.f, qp=0.f;
    for (int i=tid;i<Hd;i+=256){ float a=q[i], b=p[i];
        qq=fmaf(a,a,qq); pp=fmaf(b,b,pp); qp=fmaf(a,b,qp); }
    __shared__ float r0[256], r1[256], r2[256];
    r0[tid]=qq; r1[tid]=pp; r2[tid]=qp; __syncthreads();
    for (int o=128;o>0;o>>=1){
        if (tid<o){ r0[tid]+=r0[tid+o]; r1[tid]+=r1[tid+o]; r2[tid]+=r2[tid+o]; }
        __syncthreads();
    }
    if (tid==0){
        float d = fmaxf(sqrtf(r0[0]),1e-12f)*fmaxf(sqrtf(r1[0]),1e-12f);
        out[qb*Bp+pb] = r2[0]/d*INV_TEMP;
    }
}

/* ---------------- sparse dedup + scoring ---------------- */
__global__ void canon_kernel(const int* __restrict__ ids, const float* __restrict__ tw,
                             float* __restrict__ weff, int L)
{
    __shared__ int   sid[512];
    __shared__ float stw[512];
    int b = blockIdx.x, i = threadIdx.x;
    int base = b*L;
    sid[i] = ids[base+i]; stw[i] = tw[base+i];
    __syncthreads();
    float w = stw[i]; int id = sid[i];
    if (id < 4) w = 0.f;
    else {
        for (int j=0;j<L;j++){
            if (j!=i && sid[j]==id){
                float wj = stw[j];
                if (wj > w || (wj==w && j<i)) { w=0.f; break; }
            }
        }
    }
    weff[base+i] = w;
}

__global__ void sparse_score_kernel(const int* __restrict__ q_ids, const float* __restrict__ wq,
                                    const int* __restrict__ p_ids, const float* __restrict__ wp,
                                    float* __restrict__ out)
{
    __shared__ int   spid[Lp];
    __shared__ float spw[Lp];
    __shared__ float red[256];
    int pb=blockIdx.x, qb=blockIdx.y, tid=threadIdx.x;
    for (int j=tid;j<Lp;j+=256){ spid[j]=p_ids[pb*Lp+j]; spw[j]=wp[pb*Lp+j]; }
    __syncthreads();
    float s = 0.f;
    if (tid < Lq){
        int id = q_ids[qb*Lq+tid]; float w = wq[qb*Lq+tid];
        if (w > 0.f){
            for (int j=0;j<Lp;j++) if (spid[j]==id) s = fmaf(w, spw[j], s);
        }
    }
    red[tid]=s; __syncthreads();
    for (int o=128;o>0;o>>=1){ if (tid<o) red[tid]+=red[tid+o]; __syncthreads(); }
    if (tid==0) out[Bq*Bp + qb*Bp+pb] = red[0]*INV_TEMP;
}

__global__ void colbert_final_kernel(const float* __restrict__ qmax,
                                     const float* __restrict__ q_mask,
                                     float* __restrict__ out)
{
    int pb=blockIdx.x, qb=blockIdx.y, tid=threadIdx.x;  /* 128 threads */
    float v=0.f, mm=0.f;
    if (tid < Lq-1){
        v  = qmax[(qb*(Lq-1)+tid)*Bp + pb];
        mm = q_mask[qb*Lq + tid + 1];
    }
    __shared__ float rv[128], rm[128];
    rv[tid]=v; rm[tid]=mm; __syncthreads();
    for (int o=64;o>0;o>>=1){ if (tid<o){ rv[tid]+=rv[tid+o]; rm[tid]+=rm[tid+o]; } __syncthreads(); }
    if (tid==0) out[2*Bq*Bp + qb*Bp+pb] = rv[0]/rm[0]*INV_TEMP;
}

/* ---------------- launcher ---------------- */
extern "C" void kernel_launch(void* const* d_in, const int* in_sizes, int n_in,
                              void* d_out, int out_size)
{
    const float* q_hidden  = (const float*)d_in[0];
    const float* p_hidden  = (const float*)d_in[1];
    const float* q_mask    = (const float*)d_in[2];
    const float* p_mask    = (const float*)d_in[3];
    const int*   q_ids     = (const int*)  d_in[4];
    const int*   p_ids     = (const int*)  d_in[5];
    const float* colbert_w = (const float*)d_in[6];
    const float* colbert_b = (const float*)d_in[7];
    const float* sparse_w  = (const float*)d_in[8];
    const float* sparse_b  = (const float*)d_in[9];
    float* out = (float*)d_out;

    static float *p_tw_q=nullptr,*p_wq=nullptr,*p_tw_p=nullptr,*p_wp=nullptr,
                 *p_qmax=nullptr,*p_ssq_q=nullptr,*p_ssq_p=nullptr;
    static __nv_bfloat16 *p_qh=nullptr,*p_ph=nullptr,*p_w=nullptr,*p_Qcb=nullptr,*p_Pcb=nullptr;
    if (!p_tw_q){
        cudaGetSymbolAddress((void**)&p_tw_q, g_tw_q);
        cudaGetSymbolAddress((void**)&p_wq,   g_wq);
        cudaGetSymbolAddress((void**)&p_tw_p, g_tw_p);
        cudaGetSymbolAddress((void**)&p_wp,   g_wp);
        cudaGetSymbolAddress((void**)&p_qmax, g_qmax);
        cudaGetSymbolAddress((void**)&p_ssq_q, g_ssq_q);
        cudaGetSymbolAddress((void**)&p_ssq_p, g_ssq_p);
        cudaGetSymbolAddress((void**)&p_qh,   g_qh_bf);
        cudaGetSymbolAddress((void**)&p_ph,   g_ph_bf);
        cudaGetSymbolAddress((void**)&p_w,    g_w_bf);
        cudaGetSymbolAddress((void**)&p_Qcb,  g_Qcb);
        cudaGetSymbolAddress((void**)&p_Pcb,  g_Pcb);
        cudaFuncSetAttribute(proj_mma,   cudaFuncAttributeMaxDynamicSharedMemorySize, SMEM_TOTAL);
        cudaFuncSetAttribute(maxsim_mma, cudaFuncAttributeMaxDynamicSharedMemorySize, SMEM_TOTAL);
    }

    dim3 gQP(Bp, Bq);

    /* fused convert + sparse token weights; weight-matrix convert */
    cvt_tw_kernel<<<Bq*Lq, 128>>>(q_hidden, sparse_w, sparse_b, p_qh, p_tw_q);
    cvt_tw_kernel<<<Bp*Lp, 128>>>(p_hidden, sparse_w, sparse_b, p_ph, p_tw_p);
    f2bf_kernel<<<(Hd*Hd/4 + 255)/256, 256>>>(colbert_w, p_w, Hd*Hd/4);

    /* dense */
    dense_kernel<<<gQP, 256>>>(q_hidden, p_hidden, out);

    /* sparse */
    canon_kernel<<<Bq, Lq>>>(q_ids, p_tw_q, p_wq, Lq);
    canon_kernel<<<Bp, Lp>>>(p_ids, p_tw_p, p_wp, Lp);
    sparse_score_kernel<<<gQP, 256>>>(q_ids, p_wq, p_ids, p_wp, out);

    /* colbert projections: GEMM + fused bias/mask epilogue -> bf16, then norm scale */
    proj_mma<<<dim3(Hd/128, (MQ+127)/128), 256, SMEM_TOTAL>>>(p_qh, p_w, p_Qcb, p_ssq_q, colbert_b, q_mask, MQ, Lq);
    scale_norm<<<MQ, 128>>>(p_Qcb, p_ssq_q);
    proj_mma<<<dim3(Hd/128, (MP+127)/128), 256, SMEM_TOTAL>>>(p_ph, p_w, p_Pcb, p_ssq_p, colbert_b, p_mask, MP, Lp);
    scale_norm<<<MP, 128>>>(p_Pcb, p_ssq_p);

    /* fused maxsim GEMM + reduction */
    maxsim_mma<<<dim3(Bp, (MQ+127)/128), 256, SMEM_TOTAL>>>(p_Qcb, p_Pcb, p_qmax);
    colbert_final_kernel<<<gQP, 128>>>(p_qmax, q_mask, out);
}

// round 6
// speedup vs baseline: 6.5499x; 1.0412x over previous
#include <cuda_runtime.h>
#include <cuda_bf16.h>
#include <math.h>
#include <stdint.h>

#define Bq 8
#define Lq 128
#define Bp 64
#define Lp 512
#define Hd 1024
#define MQ (Bq*(Lq-1))   /* 1016  */
#define MP (Bp*(Lp-1))   /* 32704 */
#define INV_TEMP 50.0f

/* GEMM: block 128x128, K-stage 64, 3-stage cp.async ring, swizzled smem (no pad) */
#define KS   64
#define NSTG (Hd/KS)          /* 16 */
#define ROWB 128              /* bytes per row (KS=64 bf16), SW128 swizzled */
#define TILEB (128*ROWB)      /* 16384 B */
#define STGB  (2*TILEB)       /* 32768 B */
#define NPIPE 3
#define RED_OFF (NPIPE*STGB)  /* 98304 */
#define SMEM_TOTAL (RED_OFF + 128*2*4)   /* 99328 B -> 2 CTA/SM */

/* ---------------- scratch (allocation-free: device globals) ---------------- */
__device__ float g_tw_q[Bq*Lq];
__device__ float g_wq[Bq*Lq];
__device__ float g_tw_p[Bp*Lp];
__device__ float g_wp[Bp*Lp];
__device__ float g_qmax[MQ*Bp];
__device__ float g_ssq_q[MQ*16];
__device__ float g_ssq_p[(size_t)MP*16];
__device__ __align__(256) __nv_bfloat16 g_qh_bf[(size_t)Bq*Lq*Hd];
__device__ __align__(256) __nv_bfloat16 g_ph_bf[(size_t)Bp*Lp*Hd];
__device__ __align__(256) __nv_bfloat16 g_w_bf[(size_t)Hd*Hd];
__device__ __align__(256) __nv_bfloat16 g_Qcb[(size_t)MQ*Hd];
__device__ __align__(256) __nv_bfloat16 g_Pcb[(size_t)MP*Hd];

/* ---------------- helpers ---------------- */
__device__ __forceinline__ uint32_t sw128(uint32_t o){ return o ^ ((o>>3)&0x70u); }

__device__ __forceinline__ void mma_bf16(float* c, const unsigned* a, const unsigned* b){
    asm volatile("mma.sync.aligned.m16n8k16.row.col.f32.bf16.bf16.f32 "
        "{%0,%1,%2,%3}, {%4,%5,%6,%7}, {%8,%9}, {%0,%1,%2,%3};"
        : "+f"(c[0]), "+f"(c[1]), "+f"(c[2]), "+f"(c[3])
        : "r"(a[0]), "r"(a[1]), "r"(a[2]), "r"(a[3]), "r"(b[0]), "r"(b[1]));
}
__device__ __forceinline__ void ldm_x4(unsigned& r0, unsigned& r1, unsigned& r2, unsigned& r3, unsigned addr){
    asm volatile("ldmatrix.sync.aligned.m8n8.x4.shared.b16 {%0,%1,%2,%3}, [%4];"
        : "=r"(r0), "=r"(r1), "=r"(r2), "=r"(r3) : "r"(addr));
}
__device__ __forceinline__ void cpa16(unsigned dst, const void* src, unsigned sz){
    asm volatile("cp.async.cg.shared.global [%0], [%1], 16, %2;" :: "r"(dst), "l"(src), "r"(sz));
}
#define CP_COMMIT() asm volatile("cp.async.commit_group;" ::: "memory")
#define CP_WAIT1()  asm volatile("cp.async.wait_group 1;" ::: "memory")
#define CP_WAIT0()  asm volatile("cp.async.wait_group 0;" ::: "memory")

/* compute 4 k-steps (K=64 stage) for warp tile 32x64, swizzled smem */
__device__ __forceinline__ void mma_stage64(unsigned abase, unsigned bbase,
                                            int lane, int wm, int wn, float acc[2][8][4])
{
    #pragma unroll
    for (int k=0;k<4;k++){
        int klo = k*16;
        unsigned a[2][4];
        int m_i = lane>>3;
        int arow = ((m_i&1)<<3) + (lane&7);
        int acol = klo + ((m_i>>1)<<3);
        #pragma unroll
        for (int mt=0; mt<2; mt++){
            unsigned addr = abase + sw128((unsigned)((wm*32 + mt*16 + arow)*ROWB + acol*2));
            ldm_x4(a[mt][0], a[mt][1], a[mt][2], a[mt][3], addr);
        }
        unsigned b[4][4];
        int brow = (lane&7) + ((lane>>4)<<3);
        int bcol = klo + (((lane>>3)&1)<<3);
        #pragma unroll
        for (int bpi=0; bpi<4; bpi++){
            unsigned addr = bbase + sw128((unsigned)((wn*64 + bpi*16 + brow)*ROWB + bcol*2));
            ldm_x4(b[bpi][0], b[bpi][1], b[bpi][2], b[bpi][3], addr);
        }
        #pragma unroll
        for (int mt=0; mt<2; mt++)
            #pragma unroll
            for (int nt=0; nt<8; nt++)
                mma_bf16(acc[mt][nt], a[mt], &b[nt>>1][(nt&1)*2]);
    }
}

/* ---------------- projection GEMM + fused bias/mask epilogue, bf16 out ---------------- */
__global__ void __launch_bounds__(256,2)
proj_mma(const __nv_bfloat16* __restrict__ A, const __nv_bfloat16* __restrict__ W,
         __nv_bfloat16* __restrict__ Cb, float* __restrict__ ssq,
         const float* __restrict__ bias, const float* __restrict__ mask,
         int M, int La)
{
    extern __shared__ __align__(1024) char smem[];
    unsigned sb = (unsigned)__cvta_generic_to_shared(smem);
    int tid = threadIdx.x, lane = tid&31, wid = tid>>5;
    int wm = wid>>1, wn = wid&1;
    int blkM = blockIdx.y*128, blkN = blockIdx.x*128;
    int Lm1 = La - 1;

    const __nv_bfloat16* ap[4]; unsigned aofs[4]; unsigned asz[4];
    const __nv_bfloat16* bp[4]; unsigned bofs[4];
    #pragma unroll
    for (int i=0;i<4;i++){
        int id = tid + i*256, r = id>>3, c = id&7;
        int gr = blkM + r;
        asz[i] = (gr < M) ? 16u : 0u;
        long srow = (gr < M) ? ((long)(gr/Lm1)*La + gr%Lm1 + 1) : 0;
        ap[i] = A + srow*(long)Hd + c*8;
        aofs[i] = sw128((unsigned)(r*ROWB + c*16));
        bp[i] = W + ((long)(blkN + r))*Hd + c*8;
        bofs[i] = TILEB + sw128((unsigned)(r*ROWB + c*16));
    }

    float acc[2][8][4];
    #pragma unroll
    for (int mt=0;mt<2;mt++) for (int nt=0;nt<8;nt++) for (int j=0;j<4;j++) acc[mt][nt][j]=0.f;

    /* prefetch stages 0,1 */
    #pragma unroll
    for (int p=0;p<2;p++){
        unsigned st = sb + p*STGB;
        int k0 = p*KS;
        #pragma unroll
        for (int i=0;i<4;i++){ cpa16(st + aofs[i], ap[i] + k0, asz[i]); cpa16(st + bofs[i], bp[i] + k0, 16u); }
        CP_COMMIT();
    }

    unsigned bufofs[NPIPE] = {0u, STGB, 2u*STGB};
    #pragma unroll 1
    for (int s=0; s<NSTG; s++){
        if (s+2 < NSTG){
            CP_WAIT1();
            __syncthreads();
            unsigned st = sb + bufofs[(s+2)%NPIPE];
            int k0 = (s+2)*KS;
            #pragma unroll
            for (int i=0;i<4;i++){ cpa16(st + aofs[i], ap[i] + k0, asz[i]); cpa16(st + bofs[i], bp[i] + k0, 16u); }
            CP_COMMIT();
        } else if (s+2 == NSTG){
            CP_WAIT0();
            __syncthreads();
        }
        unsigned cs = sb + bufofs[s%NPIPE];
        mma_stage64(cs, cs + TILEB, lane, wm, wn, acc);
    }

    /* epilogue: bias + mask, partial sumsq, bf16 store */
    #pragma unroll
    for (int mt=0;mt<2;mt++){
        #pragma unroll
        for (int half=0; half<2; half++){
            int gr = blkM + wm*32 + mt*16 + (lane>>2) + half*8;
            bool valid = gr < M;
            float m = 0.f;
            if (valid) m = mask[(gr/Lm1)*La + gr%Lm1 + 1];
            float ss = 0.f;
            #pragma unroll
            for (int nt=0;nt<8;nt++){
                int gc = blkN + wn*64 + nt*8 + 2*(lane&3);
                float v0 = (acc[mt][nt][half*2+0] + bias[gc])   * m;
                float v1 = (acc[mt][nt][half*2+1] + bias[gc+1]) * m;
                ss = fmaf(v0,v0, fmaf(v1,v1, ss));
                if (valid){
                    __nv_bfloat162 bv = __floats2bfloat162_rn(v0, v1);
                    *(__nv_bfloat162*)(Cb + (size_t)gr*Hd + gc) = bv;
                }
            }
            ss += __shfl_xor_sync(0xffffffffu, ss, 1);
            ss += __shfl_xor_sync(0xffffffffu, ss, 2);
            if (valid && (lane&3)==0)
                ssq[(size_t)gr*16 + blockIdx.x*2 + wn] = ss;
        }
    }
}

/* ---------------- L2-norm scale in place (bf16) ---------------- */
__global__ void scale_norm(__nv_bfloat16* __restrict__ Cb, const float* __restrict__ ssq)
{
    int row = blockIdx.x, tid = threadIdx.x;   /* 128 threads */
    __shared__ float sinv;
    if (tid == 0){
        float ss = 0.f;
        #pragma unroll
        for (int i=0;i<16;i++) ss += ssq[(size_t)row*16 + i];
        sinv = 1.0f / fmaxf(sqrtf(ss), 1e-12f);
    }
    __syncthreads();
    float inv = sinv;
    uint4 v = *(uint4*)(Cb + (size_t)row*Hd + tid*8);
    __nv_bfloat162* pv = (__nv_bfloat162*)&v;
    #pragma unroll
    for (int j=0;j<4;j++){
        float2 f = __bfloat1622float2(pv[j]);
        pv[j] = __floats2bfloat162_rn(f.x*inv, f.y*inv);
    }
    *(uint4*)(Cb + (size_t)row*Hd + tid*8) = v;
}

/* ---------------- fused maxsim GEMM: flattened 64-stage pipeline ---------------- */
__global__ void __launch_bounds__(256,2)
maxsim_mma(const __nv_bfloat16* __restrict__ Qcb, const __nv_bfloat16* __restrict__ Pcb,
           float* __restrict__ qmax)
{
    extern __shared__ __align__(1024) char smem[];
    unsigned sb = (unsigned)__cvta_generic_to_shared(smem);
    float* red = (float*)(smem + RED_OFF);
    int tid = threadIdx.x, lane = tid&31, wid = tid>>5;
    int wm = wid>>1, wn = wid&1;
    int pb = blockIdx.x, qtile = blockIdx.y;
    int blkM = qtile*128;

    const __nv_bfloat16* ap[4]; unsigned aofs[4]; unsigned asz[4];
    const __nv_bfloat16* bp[4]; unsigned bofs[4]; int brr[4];
    const __nv_bfloat16* Pbase = Pcb + (size_t)pb*(Lp-1)*Hd;
    #pragma unroll
    for (int i=0;i<4;i++){
        int id = tid + i*256, r = id>>3, c = id&7;
        int gr = blkM + r;
        asz[i] = (gr < MQ) ? 16u : 0u;
        ap[i] = Qcb + ((size_t)(gr < MQ ? gr : 0))*Hd + c*8;
        aofs[i] = sw128((unsigned)(r*ROWB + c*16));
        brr[i] = r;
        bp[i] = Pbase + (size_t)r*Hd + c*8;
        bofs[i] = TILEB + sw128((unsigned)(r*ROWB + c*16));
    }

    float runmax[2][2];
    runmax[0][0]=runmax[0][1]=runmax[1][0]=runmax[1][1]=-1e30f;

    const int TSTG = 4*NSTG;   /* 64 flattened stages: nc = t>>4, s = t&15 */
    unsigned bufofs[NPIPE] = {0u, STGB, 2u*STGB};

    /* stage-issue helper expanded inline: stage t into buffer */
    #define ISSUE_STAGE(t_, st_) do{                                            \
        int nc_ = (t_)>>4;                                                      \
        int k0_ = ((t_)&15)*KS;                                                 \
        long bsh_ = (long)nc_*128*Hd;                                           \
        _Pragma("unroll")                                                       \
        for (int i=0;i<4;i++){                                                  \
            unsigned bsz_ = (nc_*128 + brr[i] < Lp-1) ? 16u : 0u;               \
            cpa16((st_) + aofs[i], ap[i] + k0_, asz[i]);                        \
            cpa16((st_) + bofs[i], bp[i] + bsh_ + k0_, bsz_);                   \
        }                                                                       \
        CP_COMMIT();                                                            \
    }while(0)

    ISSUE_STAGE(0, sb + bufofs[0]);
    ISSUE_STAGE(1, sb + bufofs[1]);

    float acc[2][8][4];
    #pragma unroll
    for (int mt=0;mt<2;mt++) for (int nt=0;nt<8;nt++) for (int j=0;j<4;j++) acc[mt][nt][j]=0.f;

    #pragma unroll 1
    for (int t=0; t<TSTG; t++){
        if (t+2 < TSTG){
            CP_WAIT1();
            __syncthreads();
            ISSUE_STAGE(t+2, sb + bufofs[(t+2)%NPIPE]);
        } else if (t+2 == TSTG){
            CP_WAIT0();
            __syncthreads();
        }
        unsigned cs = sb + bufofs[t%NPIPE];
        mma_stage64(cs, cs + TILEB, lane, wm, wn, acc);

        if ((t&15) == 15){
            int nc = t>>4;
            #pragma unroll
            for (int mt=0;mt<2;mt++){
                #pragma unroll
                for (int nt=0;nt<8;nt++){
                    int c0 = nc*128 + wn*64 + nt*8 + 2*(lane&3);
                    if (c0 < Lp-1){
                        runmax[mt][0] = fmaxf(runmax[mt][0], acc[mt][nt][0]);
                        runmax[mt][1] = fmaxf(runmax[mt][1], acc[mt][nt][2]);
                    }
                    if (c0+1 < Lp-1){
                        runmax[mt][0] = fmaxf(runmax[mt][0], acc[mt][nt][1]);
                        runmax[mt][1] = fmaxf(runmax[mt][1], acc[mt][nt][3]);
                    }
                    acc[mt][nt][0]=acc[mt][nt][1]=acc[mt][nt][2]=acc[mt][nt][3]=0.f;
                }
            }
        }
    }
    #undef ISSUE_STAGE

    #pragma unroll
    for (int mt=0;mt<2;mt++){
        #pragma unroll
        for (int h=0;h<2;h++){
            runmax[mt][h] = fmaxf(runmax[mt][h], __shfl_xor_sync(0xffffffffu, runmax[mt][h], 1));
            runmax[mt][h] = fmaxf(runmax[mt][h], __shfl_xor_sync(0xffffffffu, runmax[mt][h], 2));
        }
    }
    if ((lane&3)==0){
        #pragma unroll
        for (int mt=0;mt<2;mt++){
            int row = wm*32 + mt*16 + (lane>>2);
            red[row*2 + wn]     = runmax[mt][0];
            red[(row+8)*2 + wn] = runmax[mt][1];
        }
    }
    __syncthreads();
    if (tid < 128){
        int gr = blkM + tid;
        if (gr < MQ) qmax[gr*Bp + pb] = fmaxf(red[tid*2], red[tid*2+1]);
    }
}

/* ---------------- fused f32->bf16 convert + sparse token weight ---------------- */
__global__ void cvt_tw_kernel(const float* __restrict__ hidden, const float* __restrict__ sw,
                              const float* __restrict__ sbp,
                              __nv_bfloat16* __restrict__ outbf, float* __restrict__ tw)
{
    int row = blockIdx.x, tid = threadIdx.x;   /* 128 threads, 8 f32 each */
    int lane = tid&31, wid = tid>>5;
    const float* h = hidden + (size_t)row*Hd + tid*8;
    float4 a = *(const float4*)h;
    float4 b = *(const float4*)(h+4);
    const float* w = sw + tid*8;
    float4 wa = *(const float4*)w;
    float4 wb = *(const float4*)(w+4);
    uint4 o;
    __nv_bfloat162 p0 = __floats2bfloat162_rn(a.x, a.y);
    __nv_bfloat162 p1 = __floats2bfloat162_rn(a.z, a.w);
    __nv_bfloat162 p2 = __floats2bfloat162_rn(b.x, b.y);
    __nv_bfloat162 p3 = __floats2bfloat162_rn(b.z, b.w);
    o.x = *(unsigned*)&p0; o.y = *(unsigned*)&p1; o.z = *(unsigned*)&p2; o.w = *(unsigned*)&p3;
    *(uint4*)(outbf + (size_t)row*Hd + tid*8) = o;
    float s = fmaf(a.x,wa.x, fmaf(a.y,wa.y, fmaf(a.z,wa.z, fmaf(a.w,wa.w,
              fmaf(b.x,wb.x, fmaf(b.y,wb.y, fmaf(b.z,wb.z, b.w*wb.w)))))));
    #pragma unroll
    for (int of=16;of;of>>=1) s += __shfl_xor_sync(0xffffffffu, s, of);
    __shared__ float ws[4];
    if (lane==0) ws[wid] = s;
    __syncthreads();
    if (tid==0) tw[row] = fmaxf(ws[0]+ws[1]+ws[2]+ws[3] + sbp[0], 0.f);
}

/* ---------------- f32 -> bf16 convert (weights only) ---------------- */
__global__ void f2bf_kernel(const float* __restrict__ in, __nv_bfloat16* __restrict__ out, int n4){
    int i = blockIdx.x*blockDim.x + threadIdx.x;
    if (i < n4){
        float4 v = *(const float4*)(in + (size_t)i*4);
        __nv_bfloat162 lo = __floats2bfloat162_rn(v.x, v.y);
        __nv_bfloat162 hi = __floats2bfloat162_rn(v.z, v.w);
        uint2 o; o.x = *(unsigned*)&lo; o.y = *(unsigned*)&hi;
        *(uint2*)(out + (size_t)i*4) = o;
    }
}

/* ---------------- dense: CLS cosine / TEMP ---------------- */
__global__ void dense_kernel(const float* __restrict__ qh, const float* __restrict__ ph,
                             float* __restrict__ out)
{
    int pb = blockIdx.x, qb = blockIdx.y, tid = threadIdx.x;
    const float* q = qh + (size_t)qb*Lq*Hd;
    const float* p = ph + (size_t)pb*Lp*Hd;
    float qq=0.f, pp=0.f, qp=0.f;
    for (int i=tid;i<Hd;i+=256){ float a=q[i], b=p[i];
        qq=fmaf(a,a,qq); pp=fmaf(b,b,pp); qp=fmaf(a,b,qp); }
    __shared__ float r0[256], r1[256], r2[256];
    r0[tid]=qq; r1[tid]=pp; r2[tid]=qp; __syncthreads();
    for (int o=128;o>0;o>>=1){
        if (tid<o){ r0[tid]+=r0[tid+o]; r1[tid]+=r1[tid+o]; r2[tid]+=r2[tid+o]; }
        __syncthreads();
    }
    if (tid==0){
        float d = fmaxf(sqrtf(r0[0]),1e-12f)*fmaxf(sqrtf(r1[0]),1e-12f);
        out[qb*Bp+pb] = r2[0]/d*INV_TEMP;
    }
}

/* ---------------- sparse dedup + scoring ---------------- */
__global__ void canon_kernel(const int* __restrict__ ids, const float* __restrict__ tw,
                             float* __restrict__ weff, int L)
{
    __shared__ int   sid[512];
    __shared__ float stw[512];
    int b = blockIdx.x, i = threadIdx.x;
    int base = b*L;
    sid[i] = ids[base+i]; stw[i] = tw[base+i];
    __syncthreads();
    float w = stw[i]; int id = sid[i];
    if (id < 4) w = 0.f;
    else {
        for (int j=0;j<L;j++){
            if (j!=i && sid[j]==id){
                float wj = stw[j];
                if (wj > w || (wj==w && j<i)) { w=0.f; break; }
            }
        }
    }
    weff[base+i] = w;
}

__global__ void sparse_score_kernel(const int* __restrict__ q_ids, const float* __restrict__ wq,
                                    const int* __restrict__ p_ids, const float* __restrict__ wp,
                                    float* __restrict__ out)
{
    __shared__ int   spid[Lp];
    __shared__ float spw[Lp];
    __shared__ float red[256];
    int pb=blockIdx.x, qb=blockIdx.y, tid=threadIdx.x;
    for (int j=tid;j<Lp;j+=256){ spid[j]=p_ids[pb*Lp+j]; spw[j]=wp[pb*Lp+j]; }
    __syncthreads();
    float s = 0.f;
    if (tid < Lq){
        int id = q_ids[qb*Lq+tid]; float w = wq[qb*Lq+tid];
        if (w > 0.f){
            for (int j=0;j<Lp;j++) if (spid[j]==id) s = fmaf(w, spw[j], s);
        }
    }
    red[tid]=s; __syncthreads();
    for (int o=128;o>0;o>>=1){ if (tid<o) red[tid]+=red[tid+o]; __syncthreads(); }
    if (tid==0) out[Bq*Bp + qb*Bp+pb] = red[0]*INV_TEMP;
}

__global__ void colbert_final_kernel(const float* __restrict__ qmax,
                                     const float* __restrict__ q_mask,
                                     float* __restrict__ out)
{
    int pb=blockIdx.x, qb=blockIdx.y, tid=threadIdx.x;  /* 128 threads */
    float v=0.f, mm=0.f;
    if (tid < Lq-1){
        v  = qmax[(qb*(Lq-1)+tid)*Bp + pb];
        mm = q_mask[qb*Lq + tid + 1];
    }
    __shared__ float rv[128], rm[128];
    rv[tid]=v; rm[tid]=mm; __syncthreads();
    for (int o=64;o>0;o>>=1){ if (tid<o){ rv[tid]+=rv[tid+o]; rm[tid]+=rm[tid+o]; } __syncthreads(); }
    if (tid==0) out[2*Bq*Bp + qb*Bp+pb] = rv[0]/rm[0]*INV_TEMP;
}

/* ---------------- launcher ---------------- */
extern "C" void kernel_launch(void* const* d_in, const int* in_sizes, int n_in,
                              void* d_out, int out_size)
{
    const float* q_hidden  = (const float*)d_in[0];
    const float* p_hidden  = (const float*)d_in[1];
    const float* q_mask    = (const float*)d_in[2];
    const float* p_mask    = (const float*)d_in[3];
    const int*   q_ids     = (const int*)  d_in[4];
    const int*   p_ids     = (const int*)  d_in[5];
    const float* colbert_w = (const float*)d_in[6];
    const float* colbert_b = (const float*)d_in[7];
    const float* sparse_w  = (const float*)d_in[8];
    const float* sparse_b  = (const float*)d_in[9];
    float* out = (float*)d_out;

    static float *p_tw_q=nullptr,*p_wq=nullptr,*p_tw_p=nullptr,*p_wp=nullptr,
                 *p_qmax=nullptr,*p_ssq_q=nullptr,*p_ssq_p=nullptr;
    static __nv_bfloat16 *p_qh=nullptr,*p_ph=nullptr,*p_w=nullptr,*p_Qcb=nullptr,*p_Pcb=nullptr;
    if (!p_tw_q){
        cudaGetSymbolAddress((void**)&p_tw_q, g_tw_q);
        cudaGetSymbolAddress((void**)&p_wq,   g_wq);
        cudaGetSymbolAddress((void**)&p_tw_p, g_tw_p);
        cudaGetSymbolAddress((void**)&p_wp,   g_wp);
        cudaGetSymbolAddress((void**)&p_qmax, g_qmax);
        cudaGetSymbolAddress((void**)&p_ssq_q, g_ssq_q);
        cudaGetSymbolAddress((void**)&p_ssq_p, g_ssq_p);
        cudaGetSymbolAddress((void**)&p_qh,   g_qh_bf);
        cudaGetSymbolAddress((void**)&p_ph,   g_ph_bf);
        cudaGetSymbolAddress((void**)&p_w,    g_w_bf);
        cudaGetSymbolAddress((void**)&p_Qcb,  g_Qcb);
        cudaGetSymbolAddress((void**)&p_Pcb,  g_Pcb);
        cudaFuncSetAttribute(proj_mma,   cudaFuncAttributeMaxDynamicSharedMemorySize, SMEM_TOTAL);
        cudaFuncSetAttribute(maxsim_mma, cudaFuncAttributeMaxDynamicSharedMemorySize, SMEM_TOTAL);
    }

    dim3 gQP(Bp, Bq);

    /* launches 0-2: converts (+ fused sparse token weights) */
    cvt_tw_kernel<<<Bq*Lq, 128>>>(q_hidden, sparse_w, sparse_b, p_qh, p_tw_q);
    cvt_tw_kernel<<<Bp*Lp, 128>>>(p_hidden, sparse_w, sparse_b, p_ph, p_tw_p);
    f2bf_kernel<<<(Hd*Hd/4 + 255)/256, 256>>>(colbert_w, p_w, Hd*Hd/4);

    /* launches 3-4 */
    proj_mma<<<dim3(Hd/128, (MQ+127)/128), 256, SMEM_TOTAL>>>(p_qh, p_w, p_Qcb, p_ssq_q, colbert_b, q_mask, MQ, Lq);
    scale_norm<<<MQ, 128>>>(p_Qcb, p_ssq_q);

    /* launch 5 (ncu -s 5 -c 1 captures this): the big projection GEMM */
    proj_mma<<<dim3(Hd/128, (MP+127)/128), 256, SMEM_TOTAL>>>(p_ph, p_w, p_Pcb, p_ssq_p, colbert_b, p_mask, MP, Lp);
    scale_norm<<<MP, 128>>>(p_Pcb, p_ssq_p);

    /* independent small kernels */
    dense_kernel<<<gQP, 256>>>(q_hidden, p_hidden, out);
    canon_kernel<<<Bq, Lq>>>(q_ids, p_tw_q, p_wq, Lq);
    canon_kernel<<<Bp, Lp>>>(p_ids, p_tw_p, p_wp, Lp);
    sparse_score_kernel<<<gQP, 256>>>(q_ids, p_wq, p_ids, p_wp, out);

    /* fused maxsim GEMM + reduction */
    maxsim_mma<<<dim3(Bp, (MQ+127)/128), 256, SMEM_TOTAL>>>(p_Qcb, p_Pcb, p_qmax);
    colbert_final_kernel<<<gQP, 128>>>(p_qmax, q_mask, out);
}

// round 7
// speedup vs baseline: 6.9160x; 1.0559x over previous
#include <cuda_runtime.h>
#include <cuda_bf16.h>
#include <math.h>
#include <stdint.h>

#define Bq 8
#define Lq 128
#define Bp 64
#define Lp 512
#define Hd 1024
#define MQ (Bq*(Lq-1))   /* 1016  */
#define MP (Bp*(Lp-1))   /* 32704 */
#define QTILES 8         /* ceil(MQ/128) */
#define PTILES 256       /* ceil(MP/128) */
#define INV_TEMP 50.0f

/* GEMM: block 128x128, 4 warps (2Mx2N), warp tile 64x64, K-stage 64, 3-stage ring */
#define KS   64
#define NSTG (Hd/KS)          /* 16 */
#define ROWB 128              /* bytes per row, SW128 swizzled */
#define TILEB (128*ROWB)      /* 16384 B */
#define STGB  (2*TILEB)       /* 32768 B */
#define NPIPE 3
#define RED_OFF (NPIPE*STGB)  /* 98304 */
#define SMEM_TOTAL (RED_OFF + 128*2*4)   /* 99328 B -> 2 CTA/SM */

/* ---------------- scratch (allocation-free: device globals) ---------------- */
__device__ float g_tw_q[Bq*Lq];
__device__ float g_wq[Bq*Lq];
__device__ float g_tw_p[Bp*Lp];
__device__ float g_wp[Bp*Lp];
__device__ float g_qmax[MQ*Bp];
__device__ float g_ssq_q[MQ*16];
__device__ float g_ssq_p[(size_t)MP*16];
__device__ __align__(256) __nv_bfloat16 g_qh_bf[(size_t)Bq*Lq*Hd];
__device__ __align__(256) __nv_bfloat16 g_ph_bf[(size_t)Bp*Lp*Hd];
__device__ __align__(256) __nv_bfloat16 g_w_bf[(size_t)Hd*Hd];
__device__ __align__(256) __nv_bfloat16 g_Qcb[(size_t)MQ*Hd];
__device__ __align__(256) __nv_bfloat16 g_Pcb[(size_t)MP*Hd];

/* ---------------- helpers ---------------- */
__device__ __forceinline__ uint32_t sw128(uint32_t o){ return o ^ ((o>>3)&0x70u); }

__device__ __forceinline__ void mma_bf16(float* c, const unsigned* a, const unsigned* b){
    asm volatile("mma.sync.aligned.m16n8k16.row.col.f32.bf16.bf16.f32 "
        "{%0,%1,%2,%3}, {%4,%5,%6,%7}, {%8,%9}, {%0,%1,%2,%3};"
        : "+f"(c[0]), "+f"(c[1]), "+f"(c[2]), "+f"(c[3])
        : "r"(a[0]), "r"(a[1]), "r"(a[2]), "r"(a[3]), "r"(b[0]), "r"(b[1]));
}
__device__ __forceinline__ void ldm_x4(unsigned& r0, unsigned& r1, unsigned& r2, unsigned& r3, unsigned addr){
    asm volatile("ldmatrix.sync.aligned.m8n8.x4.shared.b16 {%0,%1,%2,%3}, [%4];"
        : "=r"(r0), "=r"(r1), "=r"(r2), "=r"(r3) : "r"(addr));
}
__device__ __forceinline__ void cpa16(unsigned dst, const void* src, unsigned sz){
    asm volatile("cp.async.cg.shared.global [%0], [%1], 16, %2;" :: "r"(dst), "l"(src), "r"(sz));
}
#define CP_COMMIT() asm volatile("cp.async.commit_group;" ::: "memory")
#define CP_WAIT1()  asm volatile("cp.async.wait_group 1;" ::: "memory")
#define CP_WAIT0()  asm volatile("cp.async.wait_group 0;" ::: "memory")

/* K=64 stage for warp tile 64x64: per kstep 8 ldsm.x4 -> 32 mma */
__device__ __forceinline__ void mma_stage64(unsigned abase, unsigned bbase,
                                            int lane, int wm, int wn, float acc[4][8][4])
{
    #pragma unroll
    for (int k=0;k<4;k++){
        int klo = k*16;
        unsigned a[4][4];
        int m_i = lane>>3;
        int arow = ((m_i&1)<<3) + (lane&7);
        int acol = klo + ((m_i>>1)<<3);
        #pragma unroll
        for (int mt=0; mt<4; mt++){
            unsigned addr = abase + sw128((unsigned)((wm*64 + mt*16 + arow)*ROWB + acol*2));
            ldm_x4(a[mt][0], a[mt][1], a[mt][2], a[mt][3], addr);
        }
        unsigned b[4][4];
        int brow = (lane&7) + ((lane>>4)<<3);
        int bcol = klo + (((lane>>3)&1)<<3);
        #pragma unroll
        for (int bpi=0; bpi<4; bpi++){
            unsigned addr = bbase + sw128((unsigned)((wn*64 + bpi*16 + brow)*ROWB + bcol*2));
            ldm_x4(b[bpi][0], b[bpi][1], b[bpi][2], b[bpi][3], addr);
        }
        #pragma unroll
        for (int mt=0; mt<4; mt++)
            #pragma unroll
            for (int nt=0; nt<8; nt++)
                mma_bf16(acc[mt][nt], a[mt], &b[nt>>1][(nt&1)*2]);
    }
}

/* ---------------- merged Q+P projection GEMM, fused bias/mask epilogue, bf16 out ---------------- */
__global__ void __launch_bounds__(128,2)
proj_mma(const __nv_bfloat16* __restrict__ Aq, const __nv_bfloat16* __restrict__ Ap,
         const __nv_bfloat16* __restrict__ W,
         __nv_bfloat16* __restrict__ Cq, __nv_bfloat16* __restrict__ Cp,
         float* __restrict__ ssq_q, float* __restrict__ ssq_p,
         const float* __restrict__ bias,
         const float* __restrict__ maskq, const float* __restrict__ maskp)
{
    extern __shared__ __align__(1024) char smem[];
    unsigned sb = (unsigned)__cvta_generic_to_shared(smem);
    int tid = threadIdx.x, lane = tid&31, wid = tid>>5;
    int wm = wid>>1, wn = wid&1;

    bool isQ = blockIdx.y < QTILES;
    const __nv_bfloat16* A = isQ ? Aq : Ap;
    __nv_bfloat16* Cb = isQ ? Cq : Cp;
    float* ssq = isQ ? ssq_q : ssq_p;
    const float* mask = isQ ? maskq : maskp;
    int M  = isQ ? MQ : MP;
    int La = isQ ? Lq : Lp;
    int blkM = (isQ ? blockIdx.y : blockIdx.y - QTILES) * 128;
    int blkN = blockIdx.x*128;
    int Lm1 = La - 1;

    int r0 = tid>>3, c = tid&7;          /* rows r0+16i, 8B-col c */
    const __nv_bfloat16* ap[8]; unsigned asz[8];
    #pragma unroll
    for (int i=0;i<8;i++){
        int gr = blkM + r0 + 16*i;
        asz[i] = (gr < M) ? 16u : 0u;
        long srow = (gr < M) ? ((long)(gr/Lm1)*La + gr%Lm1 + 1) : 0;
        ap[i] = A + srow*(long)Hd + c*8;
    }
    unsigned aofs0 = sw128((unsigned)(r0*ROWB + c*16));
    unsigned bofs0 = TILEB + aofs0;
    const __nv_bfloat16* bp0 = W + ((long)(blkN + r0))*Hd + c*8;

    float acc[4][8][4];
    #pragma unroll
    for (int mt=0;mt<4;mt++) for (int nt=0;nt<8;nt++) for (int j=0;j<4;j++) acc[mt][nt][j]=0.f;

    #pragma unroll
    for (int p=0;p<2;p++){
        unsigned st = sb + p*STGB;
        int k0 = p*KS;
        #pragma unroll
        for (int i=0;i<8;i++){
            cpa16(st + aofs0 + i*2048, ap[i] + k0, asz[i]);
            cpa16(st + bofs0 + i*2048, bp0 + (long)i*16*Hd + k0, 16u);
        }
        CP_COMMIT();
    }

    unsigned bufofs[NPIPE] = {0u, STGB, 2u*STGB};
    #pragma unroll 1
    for (int s=0; s<NSTG; s++){
        if (s+2 < NSTG){
            CP_WAIT1();
            __syncthreads();
            unsigned st = sb + bufofs[(s+2)%NPIPE];
            int k0 = (s+2)*KS;
            #pragma unroll
            for (int i=0;i<8;i++){
                cpa16(st + aofs0 + i*2048, ap[i] + k0, asz[i]);
                cpa16(st + bofs0 + i*2048, bp0 + (long)i*16*Hd + k0, 16u);
            }
            CP_COMMIT();
        } else if (s+2 == NSTG){
            CP_WAIT0();
            __syncthreads();
        }
        unsigned cs = sb + bufofs[s%NPIPE];
        mma_stage64(cs, cs + TILEB, lane, wm, wn, acc);
    }

    /* epilogue: bias + mask, partial sumsq, bf16 store */
    #pragma unroll
    for (int mt=0;mt<4;mt++){
        #pragma unroll
        for (int half=0; half<2; half++){
            int gr = blkM + wm*64 + mt*16 + (lane>>2) + half*8;
            bool valid = gr < M;
            float m = 0.f;
            if (valid) m = mask[(gr/Lm1)*La + gr%Lm1 + 1];
            float ss = 0.f;
            #pragma unroll
            for (int nt=0;nt<8;nt++){
                int gc = blkN + wn*64 + nt*8 + 2*(lane&3);
                float v0 = (acc[mt][nt][half*2+0] + bias[gc])   * m;
                float v1 = (acc[mt][nt][half*2+1] + bias[gc+1]) * m;
                ss = fmaf(v0,v0, fmaf(v1,v1, ss));
                if (valid){
                    __nv_bfloat162 bv = __floats2bfloat162_rn(v0, v1);
                    *(__nv_bfloat162*)(Cb + (size_t)gr*Hd + gc) = bv;
                }
            }
            ss += __shfl_xor_sync(0xffffffffu, ss, 1);
            ss += __shfl_xor_sync(0xffffffffu, ss, 2);
            if (valid && (lane&3)==0)
                ssq[(size_t)gr*16 + blockIdx.x*2 + wn] = ss;
        }
    }
}

/* ---------------- merged L2-norm scale in place (bf16) ---------------- */
__global__ void scale_norm(__nv_bfloat16* __restrict__ Cq, __nv_bfloat16* __restrict__ Cp,
                           const float* __restrict__ sq, const float* __restrict__ sp)
{
    int row = blockIdx.x, tid = threadIdx.x;   /* 128 threads */
    __nv_bfloat16* Cb; const float* ssq; int r;
    if (row < MQ){ Cb = Cq; ssq = sq; r = row; }
    else         { Cb = Cp; ssq = sp; r = row - MQ; }
    __shared__ float sinv;
    if (tid == 0){
        float ss = 0.f;
        #pragma unroll
        for (int i=0;i<16;i++) ss += ssq[(size_t)r*16 + i];
        sinv = 1.0f / fmaxf(sqrtf(ss), 1e-12f);
    }
    __syncthreads();
    float inv = sinv;
    uint4 v = *(uint4*)(Cb + (size_t)r*Hd + tid*8);
    __nv_bfloat162* pv = (__nv_bfloat162*)&v;
    #pragma unroll
    for (int j=0;j<4;j++){
        float2 f = __bfloat1622float2(pv[j]);
        pv[j] = __floats2bfloat162_rn(f.x*inv, f.y*inv);
    }
    *(uint4*)(Cb + (size_t)r*Hd + tid*8) = v;
}

/* ---------------- fused maxsim GEMM: flattened 64-stage pipeline ---------------- */
__global__ void __launch_bounds__(128,2)
maxsim_mma(const __nv_bfloat16* __restrict__ Qcb, const __nv_bfloat16* __restrict__ Pcb,
           float* __restrict__ qmax)
{
    extern __shared__ __align__(1024) char smem[];
    unsigned sb = (unsigned)__cvta_generic_to_shared(smem);
    float* red = (float*)(smem + RED_OFF);
    int tid = threadIdx.x, lane = tid&31, wid = tid>>5;
    int wm = wid>>1, wn = wid&1;
    int pb = blockIdx.x, qtile = blockIdx.y;
    int blkM = qtile*128;

    int r0 = tid>>3, c = tid&7;
    unsigned asz[8];
    #pragma unroll
    for (int i=0;i<8;i++) asz[i] = (blkM + r0 + 16*i < MQ) ? 16u : 0u;
    unsigned aofs0 = sw128((unsigned)(r0*ROWB + c*16));
    unsigned bofs0 = TILEB + aofs0;
    const __nv_bfloat16* ap0 = Qcb + ((long)(blkM + r0))*Hd + c*8;
    const __nv_bfloat16* bp0 = Pcb + ((long)pb*(Lp-1) + r0)*Hd + c*8;

    float runmax[4][2];
    #pragma unroll
    for (int mt=0;mt<4;mt++){ runmax[mt][0]=-1e30f; runmax[mt][1]=-1e30f; }

    const int TSTG = 4*NSTG;   /* 64 flattened stages: nc = t>>4, s = t&15 */
    unsigned bufofs[NPIPE] = {0u, STGB, 2u*STGB};

    #define ISSUE_STAGE(t_, st_) do{                                             \
        int nc_ = (t_)>>4;                                                       \
        int k0_ = ((t_)&15)*KS;                                                  \
        _Pragma("unroll")                                                        \
        for (int i=0;i<8;i++){                                                   \
            cpa16((st_) + aofs0 + i*2048, ap0 + (long)i*16*Hd + k0_, asz[i]);    \
            unsigned bsz_ = (nc_*128 + r0 + 16*i < Lp-1) ? 16u : 0u;             \
            cpa16((st_) + bofs0 + i*2048,                                        \
                  bp0 + ((long)nc_*128 + 16*i)*Hd + k0_, bsz_);                  \
        }                                                                        \
        CP_COMMIT();                                                             \
    }while(0)

    ISSUE_STAGE(0, sb + bufofs[0]);
    ISSUE_STAGE(1, sb + bufofs[1]);

    float acc[4][8][4];
    #pragma unroll
    for (int mt=0;mt<4;mt++) for (int nt=0;nt<8;nt++) for (int j=0;j<4;j++) acc[mt][nt][j]=0.f;

    #pragma unroll 1
    for (int t=0; t<TSTG; t++){
        if (t+2 < TSTG){
            CP_WAIT1();
            __syncthreads();
            ISSUE_STAGE(t+2, sb + bufofs[(t+2)%NPIPE]);
        } else if (t+2 == TSTG){
            CP_WAIT0();
            __syncthreads();
        }
        unsigned cs = sb + bufofs[t%NPIPE];
        mma_stage64(cs, cs + TILEB, lane, wm, wn, acc);

        if ((t&15) == 15){
            int nc = t>>4;
            #pragma unroll
            for (int mt=0;mt<4;mt++){
                #pragma unroll
                for (int nt=0;nt<8;nt++){
                    int c0 = nc*128 + wn*64 + nt*8 + 2*(lane&3);
                    if (c0 < Lp-1){
                        runmax[mt][0] = fmaxf(runmax[mt][0], acc[mt][nt][0]);
                        runmax[mt][1] = fmaxf(runmax[mt][1], acc[mt][nt][2]);
                    }
                    if (c0+1 < Lp-1){
                        runmax[mt][0] = fmaxf(runmax[mt][0], acc[mt][nt][1]);
                        runmax[mt][1] = fmaxf(runmax[mt][1], acc[mt][nt][3]);
                    }
                    acc[mt][nt][0]=acc[mt][nt][1]=acc[mt][nt][2]=acc[mt][nt][3]=0.f;
                }
            }
        }
    }
    #undef ISSUE_STAGE

    #pragma unroll
    for (int mt=0;mt<4;mt++){
        #pragma unroll
        for (int h=0;h<2;h++){
            runmax[mt][h] = fmaxf(runmax[mt][h], __shfl_xor_sync(0xffffffffu, runmax[mt][h], 1));
            runmax[mt][h] = fmaxf(runmax[mt][h], __shfl_xor_sync(0xffffffffu, runmax[mt][h], 2));
        }
    }
    if ((lane&3)==0){
        #pragma unroll
        for (int mt=0;mt<4;mt++){
            int row = wm*64 + mt*16 + (lane>>2);
            red[row*2 + wn]     = runmax[mt][0];
            red[(row+8)*2 + wn] = runmax[mt][1];
        }
    }
    __syncthreads();
    {
        int gr = blkM + tid;
        if (gr < MQ) qmax[gr*Bp + pb] = fmaxf(red[tid*2], red[tid*2+1]);
    }
}

/* ---------------- fused f32->bf16 convert + sparse token weight ---------------- */
__global__ void cvt_tw_kernel(const float* __restrict__ hidden, const float* __restrict__ sw,
                              const float* __restrict__ sbp,
                              __nv_bfloat16* __restrict__ outbf, float* __restrict__ tw)
{
    int row = blockIdx.x, tid = threadIdx.x;   /* 128 threads, 8 f32 each */
    int lane = tid&31, wid = tid>>5;
    const float* h = hidden + (size_t)row*Hd + tid*8;
    float4 a = *(const float4*)h;
    float4 b = *(const float4*)(h+4);
    const float* w = sw + tid*8;
    float4 wa = *(const float4*)w;
    float4 wb = *(const float4*)(w+4);
    uint4 o;
    __nv_bfloat162 p0 = __floats2bfloat162_rn(a.x, a.y);
    __nv_bfloat162 p1 = __floats2bfloat162_rn(a.z, a.w);
    __nv_bfloat162 p2 = __floats2bfloat162_rn(b.x, b.y);
    __nv_bfloat162 p3 = __floats2bfloat162_rn(b.z, b.w);
    o.x = *(unsigned*)&p0; o.y = *(unsigned*)&p1; o.z = *(unsigned*)&p2; o.w = *(unsigned*)&p3;
    *(uint4*)(outbf + (size_t)row*Hd + tid*8) = o;
    float s = fmaf(a.x,wa.x, fmaf(a.y,wa.y, fmaf(a.z,wa.z, fmaf(a.w,wa.w,
              fmaf(b.x,wb.x, fmaf(b.y,wb.y, fmaf(b.z,wb.z, b.w*wb.w)))))));
    #pragma unroll
    for (int of=16;of;of>>=1) s += __shfl_xor_sync(0xffffffffu, s, of);
    __shared__ float ws[4];
    if (lane==0) ws[wid] = s;
    __syncthreads();
    if (tid==0) tw[row] = fmaxf(ws[0]+ws[1]+ws[2]+ws[3] + sbp[0], 0.f);
}

/* ---------------- f32 -> bf16 convert (weights only) ---------------- */
__global__ void f2bf_kernel(const float* __restrict__ in, __nv_bfloat16* __restrict__ out, int n4){
    int i = blockIdx.x*blockDim.x + threadIdx.x;
    if (i < n4){
        float4 v = *(const float4*)(in + (size_t)i*4);
        __nv_bfloat162 lo = __floats2bfloat162_rn(v.x, v.y);
        __nv_bfloat162 hi = __floats2bfloat162_rn(v.z, v.w);
        uint2 o; o.x = *(unsigned*)&lo; o.y = *(unsigned*)&hi;
        *(uint2*)(out + (size_t)i*4) = o;
    }
}

/* ---------------- dense: CLS cosine / TEMP ---------------- */
__global__ void dense_kernel(const float* __restrict__ qh, const float* __restrict__ ph,
                             float* __restrict__ out)
{
    int pb = blockIdx.x, qb = blockIdx.y, tid = threadIdx.x;
    const float* q = qh + (size_t)qb*Lq*Hd;
    const float* p = ph + (size_t)pb*Lp*Hd;
    float qq=0.f, pp=0.f, qp=0.f;
    for (int i=tid;i<Hd;i+=256){ float a=q[i], b=p[i];
        qq=fmaf(a,a,qq); pp=fmaf(b,b,pp); qp=fmaf(a,b,qp); }
    __shared__ float r0[256], r1[256], r2[256];
    r0[tid]=qq; r1[tid]=pp; r2[tid]=qp; __syncthreads();
    for (int o=128;o>0;o>>=1){
        if (tid<o){ r0[tid]+=r0[tid+o]; r1[tid]+=r1[tid+o]; r2[tid]+=r2[tid+o]; }
        __syncthreads();
    }
    if (tid==0){
        float d = fmaxf(sqrtf(r0[0]),1e-12f)*fmaxf(sqrtf(r1[0]),1e-12f);
        out[qb*Bp+pb] = r2[0]/d*INV_TEMP;
    }
}

/* ---------------- sparse dedup + scoring ---------------- */
__global__ void canon_kernel(const int* __restrict__ ids, const float* __restrict__ tw,
                             float* __restrict__ weff, int L)
{
    __shared__ int   sid[512];
    __shared__ float stw[512];
    int b = blockIdx.x, i = threadIdx.x;
    int base = b*L;
    sid[i] = ids[base+i]; stw[i] = tw[base+i];
    __syncthreads();
    float w = stw[i]; int id = sid[i];
    if (id < 4) w = 0.f;
    else {
        for (int j=0;j<L;j++){
            if (j!=i && sid[j]==id){
                float wj = stw[j];
                if (wj > w || (wj==w && j<i)) { w=0.f; break; }
            }
        }
    }
    weff[base+i] = w;
}

__global__ void sparse_score_kernel(const int* __restrict__ q_ids, const float* __restrict__ wq,
                                    const int* __restrict__ p_ids, const float* __restrict__ wp,
                                    float* __restrict__ out)
{
    __shared__ int   spid[Lp];
    __shared__ float spw[Lp];
    __shared__ float red[256];
    int pb=blockIdx.x, qb=blockIdx.y, tid=threadIdx.x;
    for (int j=tid;j<Lp;j+=256){ spid[j]=p_ids[pb*Lp+j]; spw[j]=wp[pb*Lp+j]; }
    __syncthreads();
    float s = 0.f;
    if (tid < Lq){
        int id = q_ids[qb*Lq+tid]; float w = wq[qb*Lq+tid];
        if (w > 0.f){
            for (int j=0;j<Lp;j++) if (spid[j]==id) s = fmaf(w, spw[j], s);
        }
    }
    red[tid]=s; __syncthreads();
    for (int o=128;o>0;o>>=1){ if (tid<o) red[tid]+=red[tid+o]; __syncthreads(); }
    if (tid==0) out[Bq*Bp + qb*Bp+pb] = red[0]*INV_TEMP;
}

__global__ void colbert_final_kernel(const float* __restrict__ qmax,
                                     const float* __restrict__ q_mask,
                                     float* __restrict__ out)
{
    int pb=blockIdx.x, qb=blockIdx.y, tid=threadIdx.x;  /* 128 threads */
    float v=0.f, mm=0.f;
    if (tid < Lq-1){
        v  = qmax[(qb*(Lq-1)+tid)*Bp + pb];
        mm = q_mask[qb*Lq + tid + 1];
    }
    __shared__ float rv[128], rm[128];
    rv[tid]=v; rm[tid]=mm; __syncthreads();
    for (int o=64;o>0;o>>=1){ if (tid<o){ rv[tid]+=rv[tid+o]; rm[tid]+=rm[tid+o]; } __syncthreads(); }
    if (tid==0) out[2*Bq*Bp + qb*Bp+pb] = rv[0]/rm[0]*INV_TEMP;
}

/* ---------------- launcher ---------------- */
extern "C" void kernel_launch(void* const* d_in, const int* in_sizes, int n_in,
                              void* d_out, int out_size)
{
    const float* q_hidden  = (const float*)d_in[0];
    const float* p_hidden  = (const float*)d_in[1];
    const float* q_mask    = (const float*)d_in[2];
    const float* p_mask    = (const float*)d_in[3];
    const int*   q_ids     = (const int*)  d_in[4];
    const int*   p_ids     = (const int*)  d_in[5];
    const float* colbert_w = (const float*)d_in[6];
    const float* colbert_b = (const float*)d_in[7];
    const float* sparse_w  = (const float*)d_in[8];
    const float* sparse_b  = (const float*)d_in[9];
    float* out = (float*)d_out;

    static float *p_tw_q=nullptr,*p_wq=nullptr,*p_tw_p=nullptr,*p_wp=nullptr,
                 *p_qmax=nullptr,*p_ssq_q=nullptr,*p_ssq_p=nullptr;
    static __nv_bfloat16 *p_qh=nullptr,*p_ph=nullptr,*p_w=nullptr,*p_Qcb=nullptr,*p_Pcb=nullptr;
    if (!p_tw_q){
        cudaGetSymbolAddress((void**)&p_tw_q, g_tw_q);
        cudaGetSymbolAddress((void**)&p_wq,   g_wq);
        cudaGetSymbolAddress((void**)&p_tw_p, g_tw_p);
        cudaGetSymbolAddress((void**)&p_wp,   g_wp);
        cudaGetSymbolAddress((void**)&p_qmax, g_qmax);
        cudaGetSymbolAddress((void**)&p_ssq_q, g_ssq_q);
        cudaGetSymbolAddress((void**)&p_ssq_p, g_ssq_p);
        cudaGetSymbolAddress((void**)&p_qh,   g_qh_bf);
        cudaGetSymbolAddress((void**)&p_ph,   g_ph_bf);
        cudaGetSymbolAddress((void**)&p_w,    g_w_bf);
        cudaGetSymbolAddress((void**)&p_Qcb,  g_Qcb);
        cudaGetSymbolAddress((void**)&p_Pcb,  g_Pcb);
        cudaFuncSetAttribute(proj_mma,   cudaFuncAttributeMaxDynamicSharedMemorySize, SMEM_TOTAL);
        cudaFuncSetAttribute(maxsim_mma, cudaFuncAttributeMaxDynamicSharedMemorySize, SMEM_TOTAL);
    }

    dim3 gQP(Bp, Bq);

    /* converts (+ fused sparse token weights) */
    cvt_tw_kernel<<<Bq*Lq, 128>>>(q_hidden, sparse_w, sparse_b, p_qh, p_tw_q);
    cvt_tw_kernel<<<Bp*Lp, 128>>>(p_hidden, sparse_w, sparse_b, p_ph, p_tw_p);
    f2bf_kernel<<<(Hd*Hd/4 + 255)/256, 256>>>(colbert_w, p_w, Hd*Hd/4);

    /* merged Q+P projection GEMM + norm scale */
    proj_mma<<<dim3(Hd/128, QTILES+PTILES), 128, SMEM_TOTAL>>>(
        p_qh, p_ph, p_w, p_Qcb, p_Pcb, p_ssq_q, p_ssq_p, colbert_b, q_mask, p_mask);
    scale_norm<<<MQ+MP, 128>>>(p_Qcb, p_Pcb, p_ssq_q, p_ssq_p);

    /* fused maxsim GEMM + reduction */
    maxsim_mma<<<dim3(Bp, QTILES), 128, SMEM_TOTAL>>>(p_Qcb, p_Pcb, p_qmax);

    /* independent small kernels */
    dense_kernel<<<gQP, 256>>>(q_hidden, p_hidden, out);
    canon_kernel<<<Bq, Lq>>>(q_ids, p_tw_q, p_wq, Lq);
    canon_kernel<<<Bp, Lp>>>(p_ids, p_tw_p, p_wp, Lp);
    sparse_score_kernel<<<gQP, 256>>>(q_ids, p_wq, p_ids, p_wp, out);
    colbert_final_kernel<<<gQP, 128>>>(p_qmax, q_mask, out);
}

// round 8
// speedup vs baseline: 8.5039x; 1.2296x over previous
#include <cuda_runtime.h>
#include <cuda_bf16.h>
#include <math.h>
#include <stdint.h>

#define Bq 8
#define Lq 128
#define Bp 64
#define Lp 512
#define Hd 1024
#define MQ (Bq*(Lq-1))   /* 1016  */
#define MP (Bp*(Lp-1))   /* 32704 */
#define QTILES 8
#define PTILES 256
#define INV_TEMP 50.0f

/* GEMM: block 128x128, 4 warps (2Mx2N), warp tile 64x64, K-stage 64, 3-stage ring */
#define KS   64
#define NSTG (Hd/KS)          /* 16 */
#define ROWB 128
#define TILEB (128*ROWB)      /* 16384 B */
#define STGB  (2*TILEB)       /* 32768 B */
#define NPIPE 3
#define RED_OFF (NPIPE*STGB)
#define SMEM_TOTAL (RED_OFF + 128*2*4)   /* 99328 B -> 2 CTA/SM */

/* ---------------- scratch (allocation-free: device globals) ---------------- */
__device__ float g_tw_q[Bq*Lq];
__device__ float g_wq[Bq*Lq];
__device__ float g_tw_p[Bp*Lp];
__device__ float g_wp[Bp*Lp];
__device__ float g_qmax[(size_t)MQ*Bp*4];
__device__ float g_ssq_q[MQ*16];
__device__ float g_ssq_p[(size_t)MP*16];
__device__ float g_rsq_q[MQ];
__device__ float g_rsq_p[MP];
__device__ __align__(256) __nv_bfloat16 g_qh_bf[(size_t)Bq*Lq*Hd];
__device__ __align__(256) __nv_bfloat16 g_ph_bf[(size_t)Bp*Lp*Hd];
__device__ __align__(256) __nv_bfloat16 g_w_bf[(size_t)Hd*Hd];
__device__ __align__(256) __nv_bfloat16 g_Qcb[(size_t)MQ*Hd];
__device__ __align__(256) __nv_bfloat16 g_Pcb[(size_t)MP*Hd];

/* ---------------- helpers ---------------- */
__device__ __forceinline__ uint32_t sw128(uint32_t o){ return o ^ ((o>>3)&0x70u); }

__device__ __forceinline__ void mma_bf16(float* c, const unsigned* a, const unsigned* b){
    asm volatile("mma.sync.aligned.m16n8k16.row.col.f32.bf16.bf16.f32 "
        "{%0,%1,%2,%3}, {%4,%5,%6,%7}, {%8,%9}, {%0,%1,%2,%3};"
        : "+f"(c[0]), "+f"(c[1]), "+f"(c[2]), "+f"(c[3])
        : "r"(a[0]), "r"(a[1]), "r"(a[2]), "r"(a[3]), "r"(b[0]), "r"(b[1]));
}
__device__ __forceinline__ void ldm_x4(unsigned& r0, unsigned& r1, unsigned& r2, unsigned& r3, unsigned addr){
    asm volatile("ldmatrix.sync.aligned.m8n8.x4.shared.b16 {%0,%1,%2,%3}, [%4];"
        : "=r"(r0), "=r"(r1), "=r"(r2), "=r"(r3) : "r"(addr));
}
__device__ __forceinline__ void cpa16(unsigned dst, const void* src, unsigned sz){
    asm volatile("cp.async.cg.shared.global [%0], [%1], 16, %2;" :: "r"(dst), "l"(src), "r"(sz));
}
#define CP_COMMIT() asm volatile("cp.async.commit_group;" ::: "memory")
#define CP_WAIT1()  asm volatile("cp.async.wait_group 1;" ::: "memory")
#define CP_WAIT0()  asm volatile("cp.async.wait_group 0;" ::: "memory")

/* K=64 stage for warp tile 64x64: per kstep 8 ldsm.x4 -> 32 mma */
__device__ __forceinline__ void mma_stage64(unsigned abase, unsigned bbase,
                                            int lane, int wm, int wn, float acc[4][8][4])
{
    #pragma unroll
    for (int k=0;k<4;k++){
        int klo = k*16;
        unsigned a[4][4];
        int m_i = lane>>3;
        int arow = ((m_i&1)<<3) + (lane&7);
        int acol = klo + ((m_i>>1)<<3);
        #pragma unroll
        for (int mt=0; mt<4; mt++){
            unsigned addr = abase + sw128((unsigned)((wm*64 + mt*16 + arow)*ROWB + acol*2));
            ldm_x4(a[mt][0], a[mt][1], a[mt][2], a[mt][3], addr);
        }
        unsigned b[4][4];
        int brow = (lane&7) + ((lane>>4)<<3);
        int bcol = klo + (((lane>>3)&1)<<3);
        #pragma unroll
        for (int bpi=0; bpi<4; bpi++){
            unsigned addr = bbase + sw128((unsigned)((wn*64 + bpi*16 + brow)*ROWB + bcol*2));
            ldm_x4(b[bpi][0], b[bpi][1], b[bpi][2], b[bpi][3], addr);
        }
        #pragma unroll
        for (int mt=0; mt<4; mt++)
            #pragma unroll
            for (int nt=0; nt<8; nt++)
                mma_bf16(acc[mt][nt], a[mt], &b[nt>>1][(nt&1)*2]);
    }
}

/* ---------------- merged Q+P projection GEMM, fused bias/mask epilogue, bf16 out ---------------- */
__global__ void __launch_bounds__(128,2)
proj_mma(const __nv_bfloat16* __restrict__ Aq, const __nv_bfloat16* __restrict__ Ap,
         const __nv_bfloat16* __restrict__ W,
         __nv_bfloat16* __restrict__ Cq, __nv_bfloat16* __restrict__ Cp,
         float* __restrict__ ssq_q, float* __restrict__ ssq_p,
         const float* __restrict__ bias,
         const float* __restrict__ maskq, const float* __restrict__ maskp)
{
    extern __shared__ __align__(1024) char smem[];
    unsigned sb = (unsigned)__cvta_generic_to_shared(smem);
    int tid = threadIdx.x, lane = tid&31, wid = tid>>5;
    int wm = wid>>1, wn = wid&1;

    bool isQ = blockIdx.y < QTILES;
    const __nv_bfloat16* A = isQ ? Aq : Ap;
    __nv_bfloat16* Cb = isQ ? Cq : Cp;
    float* ssq = isQ ? ssq_q : ssq_p;
    const float* mask = isQ ? maskq : maskp;
    int M  = isQ ? MQ : MP;
    int La = isQ ? Lq : Lp;
    int blkM = (isQ ? blockIdx.y : blockIdx.y - QTILES) * 128;
    int blkN = blockIdx.x*128;
    int Lm1 = La - 1;

    int r0 = tid>>3, c = tid&7;
    const __nv_bfloat16* ap[8]; unsigned asz[8];
    #pragma unroll
    for (int i=0;i<8;i++){
        int gr = blkM + r0 + 16*i;
        asz[i] = (gr < M) ? 16u : 0u;
        long srow = (gr < M) ? ((long)(gr/Lm1)*La + gr%Lm1 + 1) : 0;
        ap[i] = A + srow*(long)Hd + c*8;
    }
    unsigned aofs0 = sw128((unsigned)(r0*ROWB + c*16));
    unsigned bofs0 = TILEB + aofs0;
    const __nv_bfloat16* bp0 = W + ((long)(blkN + r0))*Hd + c*8;

    float acc[4][8][4];
    #pragma unroll
    for (int mt=0;mt<4;mt++) for (int nt=0;nt<8;nt++) for (int j=0;j<4;j++) acc[mt][nt][j]=0.f;

    #pragma unroll
    for (int p=0;p<2;p++){
        unsigned st = sb + p*STGB;
        int k0 = p*KS;
        #pragma unroll
        for (int i=0;i<8;i++){
            cpa16(st + aofs0 + i*2048, ap[i] + k0, asz[i]);
            cpa16(st + bofs0 + i*2048, bp0 + (long)i*16*Hd + k0, 16u);
        }
        CP_COMMIT();
    }

    unsigned bufofs[NPIPE] = {0u, STGB, 2u*STGB};
    #pragma unroll 1
    for (int s=0; s<NSTG; s++){
        if (s+2 < NSTG){
            CP_WAIT1();
            __syncthreads();
            unsigned st = sb + bufofs[(s+2)%NPIPE];
            int k0 = (s+2)*KS;
            #pragma unroll
            for (int i=0;i<8;i++){
                cpa16(st + aofs0 + i*2048, ap[i] + k0, asz[i]);
                cpa16(st + bofs0 + i*2048, bp0 + (long)i*16*Hd + k0, 16u);
            }
            CP_COMMIT();
        } else if (s+2 == NSTG){
            CP_WAIT0();
            __syncthreads();
        }
        unsigned cs = sb + bufofs[s%NPIPE];
        mma_stage64(cs, cs + TILEB, lane, wm, wn, acc);
    }

    /* epilogue: bias + mask, partial sumsq, bf16 store (unnormalized) */
    #pragma unroll
    for (int mt=0;mt<4;mt++){
        #pragma unroll
        for (int half=0; half<2; half++){
            int gr = blkM + wm*64 + mt*16 + (lane>>2) + half*8;
            bool valid = gr < M;
            float m = 0.f;
            if (valid) m = mask[(gr/Lm1)*La + gr%Lm1 + 1];
            float ss = 0.f;
            #pragma unroll
            for (int nt=0;nt<8;nt++){
                int gc = blkN + wn*64 + nt*8 + 2*(lane&3);
                float v0 = (acc[mt][nt][half*2+0] + bias[gc])   * m;
                float v1 = (acc[mt][nt][half*2+1] + bias[gc+1]) * m;
                ss = fmaf(v0,v0, fmaf(v1,v1, ss));
                if (valid){
                    __nv_bfloat162 bv = __floats2bfloat162_rn(v0, v1);
                    *(__nv_bfloat162*)(Cb + (size_t)gr*Hd + gc) = bv;
                }
            }
            ss += __shfl_xor_sync(0xffffffffu, ss, 1);
            ss += __shfl_xor_sync(0xffffffffu, ss, 2);
            if (valid && (lane&3)==0)
                ssq[(size_t)gr*16 + blockIdx.x*2 + wn] = ss;
        }
    }
}

/* ---------------- ssq partials -> reciprocal norms ---------------- */
__global__ void ssq_reduce(const float* __restrict__ sq, const float* __restrict__ sp,
                           float* __restrict__ rq, float* __restrict__ rp)
{
    int i = blockIdx.x*blockDim.x + threadIdx.x;
    const float* s; float* r; int idx;
    if (i < MQ){ s = sq; r = rq; idx = i; }
    else if (i < MQ+MP){ s = sp; r = rp; idx = i - MQ; }
    else return;
    float t = 0.f;
    #pragma unroll
    for (int k=0;k<16;k++) t += s[(size_t)idx*16 + k];
    r[idx] = 1.0f / fmaxf(sqrtf(t), 1e-12f);
}

/* ---------------- maxsim GEMM (quarter-split) with fused p-norm scaling ---------------- */
__global__ void __launch_bounds__(128,2)
maxsim_mma(const __nv_bfloat16* __restrict__ Qcb, const __nv_bfloat16* __restrict__ Pcb,
           const float* __restrict__ rsq_p, float* __restrict__ qmax4)
{
    extern __shared__ __align__(1024) char smem[];
    unsigned sb = (unsigned)__cvta_generic_to_shared(smem);
    float* red = (float*)(smem + RED_OFF);
    int tid = threadIdx.x, lane = tid&31, wid = tid>>5;
    int wm = wid>>1, wn = wid&1;
    int pb = blockIdx.x>>2, qc = blockIdx.x&3;
    int blkM = blockIdx.y*128;

    int r0 = tid>>3, c = tid&7;
    unsigned asz[8], bsz[8];
    #pragma unroll
    for (int i=0;i<8;i++){
        asz[i] = (blkM + r0 + 16*i < MQ) ? 16u : 0u;
        bsz[i] = (qc*128 + r0 + 16*i < Lp-1) ? 16u : 0u;
    }
    unsigned aofs0 = sw128((unsigned)(r0*ROWB + c*16));
    unsigned bofs0 = TILEB + aofs0;
    const __nv_bfloat16* ap0 = Qcb + ((long)(blkM + r0))*Hd + c*8;
    const __nv_bfloat16* bp0 = Pcb + ((long)pb*(Lp-1) + qc*128 + r0)*Hd + c*8;

    float acc[4][8][4];
    #pragma unroll
    for (int mt=0;mt<4;mt++) for (int nt=0;nt<8;nt++) for (int j=0;j<4;j++) acc[mt][nt][j]=0.f;

    #pragma unroll
    for (int p=0;p<2;p++){
        unsigned st = sb + p*STGB;
        int k0 = p*KS;
        #pragma unroll
        for (int i=0;i<8;i++){
            cpa16(st + aofs0 + i*2048, ap0 + (long)i*16*Hd + k0, asz[i]);
            cpa16(st + bofs0 + i*2048, bp0 + (long)i*16*Hd + k0, bsz[i]);
        }
        CP_COMMIT();
    }

    unsigned bufofs[NPIPE] = {0u, STGB, 2u*STGB};
    #pragma unroll 1
    for (int s=0; s<NSTG; s++){
        if (s+2 < NSTG){
            CP_WAIT1();
            __syncthreads();
            unsigned st = sb + bufofs[(s+2)%NPIPE];
            int k0 = (s+2)*KS;
            #pragma unroll
            for (int i=0;i<8;i++){
                cpa16(st + aofs0 + i*2048, ap0 + (long)i*16*Hd + k0, asz[i]);
                cpa16(st + bofs0 + i*2048, bp0 + (long)i*16*Hd + k0, bsz[i]);
            }
            CP_COMMIT();
        } else if (s+2 == NSTG){
            CP_WAIT0();
            __syncthreads();
        }
        unsigned cs = sb + bufofs[s%NPIPE];
        mma_stage64(cs, cs + TILEB, lane, wm, wn, acc);
    }

    /* fold: apply per-passage-token reciprocal norm, then running max */
    const float* spb = rsq_p + (long)pb*(Lp-1) + qc*128;
    float runmax[4][2];
    #pragma unroll
    for (int mt=0;mt<4;mt++){ runmax[mt][0]=-1e30f; runmax[mt][1]=-1e30f; }
    #pragma unroll
    for (int nt=0;nt<8;nt++){
        int c0 = wn*64 + nt*8 + 2*(lane&3);
        bool v0 = (qc*128 + c0    ) < (Lp-1);
        bool v1 = (qc*128 + c0 + 1) < (Lp-1);
        float sp0 = v0 ? spb[c0]   : 0.f;
        float sp1 = v1 ? spb[c0+1] : 0.f;
        #pragma unroll
        for (int mt=0;mt<4;mt++){
            if (v0){
                runmax[mt][0] = fmaxf(runmax[mt][0], acc[mt][nt][0]*sp0);
                runmax[mt][1] = fmaxf(runmax[mt][1], acc[mt][nt][2]*sp0);
            }
            if (v1){
                runmax[mt][0] = fmaxf(runmax[mt][0], acc[mt][nt][1]*sp1);
                runmax[mt][1] = fmaxf(runmax[mt][1], acc[mt][nt][3]*sp1);
            }
        }
    }

    #pragma unroll
    for (int mt=0;mt<4;mt++){
        #pragma unroll
        for (int h=0;h<2;h++){
            runmax[mt][h] = fmaxf(runmax[mt][h], __shfl_xor_sync(0xffffffffu, runmax[mt][h], 1));
            runmax[mt][h] = fmaxf(runmax[mt][h], __shfl_xor_sync(0xffffffffu, runmax[mt][h], 2));
        }
    }
    if ((lane&3)==0){
        #pragma unroll
        for (int mt=0;mt<4;mt++){
            int row = wm*64 + mt*16 + (lane>>2);
            red[row*2 + wn]     = runmax[mt][0];
            red[(row+8)*2 + wn] = runmax[mt][1];
        }
    }
    __syncthreads();
    {
        int gr = blkM + tid;
        if (gr < MQ)
            qmax4[(size_t)gr*(Bp*4) + blockIdx.x] = fmaxf(red[tid*2], red[tid*2+1]);
    }
}

/* ---------------- merged f32->bf16 convert + sparse token weight (Q and P) ---------------- */
__global__ void cvt_tw_all(const float* __restrict__ qh, const float* __restrict__ ph,
                           const float* __restrict__ sw, const float* __restrict__ sbp,
                           __nv_bfloat16* __restrict__ qbf, __nv_bfloat16* __restrict__ pbf,
                           float* __restrict__ twq, float* __restrict__ twp)
{
    int row = blockIdx.x, tid = threadIdx.x;
    int lane = tid&31, wid = tid>>5;
    const float* h; __nv_bfloat16* o; float* tw; int r;
    if (row < Bq*Lq){ h = qh; o = qbf; tw = twq; r = row; }
    else            { r = row - Bq*Lq; h = ph; o = pbf; tw = twp; }
    const float* hp = h + (size_t)r*Hd + tid*8;
    float4 a = *(const float4*)hp;
    float4 b = *(const float4*)(hp+4);
    const float* w = sw + tid*8;
    float4 wa = *(const float4*)w;
    float4 wb = *(const float4*)(w+4);
    uint4 ov;
    __nv_bfloat162 p0 = __floats2bfloat162_rn(a.x, a.y);
    __nv_bfloat162 p1 = __floats2bfloat162_rn(a.z, a.w);
    __nv_bfloat162 p2 = __floats2bfloat162_rn(b.x, b.y);
    __nv_bfloat162 p3 = __floats2bfloat162_rn(b.z, b.w);
    ov.x = *(unsigned*)&p0; ov.y = *(unsigned*)&p1; ov.z = *(unsigned*)&p2; ov.w = *(unsigned*)&p3;
    *(uint4*)(o + (size_t)r*Hd + tid*8) = ov;
    float s = fmaf(a.x,wa.x, fmaf(a.y,wa.y, fmaf(a.z,wa.z, fmaf(a.w,wa.w,
              fmaf(b.x,wb.x, fmaf(b.y,wb.y, fmaf(b.z,wb.z, b.w*wb.w)))))));
    #pragma unroll
    for (int of=16;of;of>>=1) s += __shfl_xor_sync(0xffffffffu, s, of);
    __shared__ float ws[4];
    if (lane==0) ws[wid] = s;
    __syncthreads();
    if (tid==0) tw[r] = fmaxf(ws[0]+ws[1]+ws[2]+ws[3] + sbp[0], 0.f);
}

/* ---------------- f32 -> bf16 convert (weights only) ---------------- */
__global__ void f2bf_kernel(const float* __restrict__ in, __nv_bfloat16* __restrict__ out, int n4){
    int i = blockIdx.x*blockDim.x + threadIdx.x;
    if (i < n4){
        float4 v = *(const float4*)(in + (size_t)i*4);
        __nv_bfloat162 lo = __floats2bfloat162_rn(v.x, v.y);
        __nv_bfloat162 hi = __floats2bfloat162_rn(v.z, v.w);
        uint2 o; o.x = *(unsigned*)&lo; o.y = *(unsigned*)&hi;
        *(uint2*)(out + (size_t)i*4) = o;
    }
}

/* ---------------- dense: CLS cosine / TEMP ---------------- */
__global__ void dense_kernel(const float* __restrict__ qh, const float* __restrict__ ph,
                             float* __restrict__ out)
{
    int pb = blockIdx.x, qb = blockIdx.y, tid = threadIdx.x;
    const float* q = qh + (size_t)qb*Lq*Hd;
    const float* p = ph + (size_t)pb*Lp*Hd;
    float qq=0.f, pp=0.f, qp=0.f;
    for (int i=tid;i<Hd;i+=256){ float a=q[i], b=p[i];
        qq=fmaf(a,a,qq); pp=fmaf(b,b,pp); qp=fmaf(a,b,qp); }
    __shared__ float r0[256], r1[256], r2[256];
    r0[tid]=qq; r1[tid]=pp; r2[tid]=qp; __syncthreads();
    for (int o=128;o>0;o>>=1){
        if (tid<o){ r0[tid]+=r0[tid+o]; r1[tid]+=r1[tid+o]; r2[tid]+=r2[tid+o]; }
        __syncthreads();
    }
    if (tid==0){
        float d = fmaxf(sqrtf(r0[0]),1e-12f)*fmaxf(sqrtf(r1[0]),1e-12f);
        out[qb*Bp+pb] = r2[0]/d*INV_TEMP;
    }
}

/* ---------------- sparse dedup + scoring ---------------- */
__global__ void canon_kernel(const int* __restrict__ ids, const float* __restrict__ tw,
                             float* __restrict__ weff, int L)
{
    __shared__ int   sid[512];
    __shared__ float stw[512];
    int b = blockIdx.x, i = threadIdx.x;
    int base = b*L;
    sid[i] = ids[base+i]; stw[i] = tw[base+i];
    __syncthreads();
    float w = stw[i]; int id = sid[i];
    if (id < 4) w = 0.f;
    else {
        for (int j=0;j<L;j++){
            if (j!=i && sid[j]==id){
                float wj = stw[j];
                if (wj > w || (wj==w && j<i)) { w=0.f; break; }
            }
        }
    }
    weff[base+i] = w;
}

__global__ void sparse_score_kernel(const int* __restrict__ q_ids, const float* __restrict__ wq,
                                    const int* __restrict__ p_ids, const float* __restrict__ wp,
                                    float* __restrict__ out)
{
    __shared__ int   spid[Lp];
    __shared__ float spw[Lp];
    __shared__ float red[256];
    int pb=blockIdx.x, qb=blockIdx.y, tid=threadIdx.x;
    for (int j=tid;j<Lp;j+=256){ spid[j]=p_ids[pb*Lp+j]; spw[j]=wp[pb*Lp+j]; }
    __syncthreads();
    float s = 0.f;
    if (tid < Lq){
        int id = q_ids[qb*Lq+tid]; float w = wq[qb*Lq+tid];
        if (w > 0.f){
            for (int j=0;j<Lp;j++) if (spid[j]==id) s = fmaf(w, spw[j], s);
        }
    }
    red[tid]=s; __syncthreads();
    for (int o=128;o>0;o>>=1){ if (tid<o) red[tid]+=red[tid+o]; __syncthreads(); }
    if (tid==0) out[Bq*Bp + qb*Bp+pb] = red[0]*INV_TEMP;
}

__global__ void colbert_final_kernel(const float* __restrict__ qmax4,
                                     const float* __restrict__ rsq_q,
                                     const float* __restrict__ q_mask,
                                     float* __restrict__ out)
{
    int pb=blockIdx.x, qb=blockIdx.y, tid=threadIdx.x;  /* 128 threads */
    float v=0.f, mm=0.f;
    if (tid < Lq-1){
        int gr = qb*(Lq-1)+tid;
        const float* qm = qmax4 + (size_t)gr*(Bp*4) + pb*4;
        float m4 = fmaxf(fmaxf(qm[0],qm[1]), fmaxf(qm[2],qm[3]));
        v  = m4 * rsq_q[gr];
        mm = q_mask[qb*Lq + tid + 1];
    }
    __shared__ float rv[128], rm[128];
    rv[tid]=v; rm[tid]=mm; __syncthreads();
    for (int o=64;o>0;o>>=1){ if (tid<o){ rv[tid]+=rv[tid+o]; rm[tid]+=rm[tid+o]; } __syncthreads(); }
    if (tid==0) out[2*Bq*Bp + qb*Bp+pb] = rv[0]/rm[0]*INV_TEMP;
}

/* ---------------- launcher ---------------- */
extern "C" void kernel_launch(void* const* d_in, const int* in_sizes, int n_in,
                              void* d_out, int out_size)
{
    const float* q_hidden  = (const float*)d_in[0];
    const float* p_hidden  = (const float*)d_in[1];
    const float* q_mask    = (const float*)d_in[2];
    const float* p_mask    = (const float*)d_in[3];
    const int*   q_ids     = (const int*)  d_in[4];
    const int*   p_ids     = (const int*)  d_in[5];
    const float* colbert_w = (const float*)d_in[6];
    const float* colbert_b = (const float*)d_in[7];
    const float* sparse_w  = (const float*)d_in[8];
    const float* sparse_b  = (const float*)d_in[9];
    float* out = (float*)d_out;

    static float *p_tw_q=nullptr,*p_wq=nullptr,*p_tw_p=nullptr,*p_wp=nullptr,
                 *p_qmax=nullptr,*p_ssq_q=nullptr,*p_ssq_p=nullptr,*p_rsq_q=nullptr,*p_rsq_p=nullptr;
    static __nv_bfloat16 *p_qh=nullptr,*p_ph=nullptr,*p_w=nullptr,*p_Qcb=nullptr,*p_Pcb=nullptr;
    static cudaStream_t s2 = nullptr;
    static cudaEvent_t evA = nullptr, evB = nullptr;
    if (!p_tw_q){
        cudaGetSymbolAddress((void**)&p_tw_q, g_tw_q);
        cudaGetSymbolAddress((void**)&p_wq,   g_wq);
        cudaGetSymbolAddress((void**)&p_tw_p, g_tw_p);
        cudaGetSymbolAddress((void**)&p_wp,   g_wp);
        cudaGetSymbolAddress((void**)&p_qmax, g_qmax);
        cudaGetSymbolAddress((void**)&p_ssq_q, g_ssq_q);
        cudaGetSymbolAddress((void**)&p_ssq_p, g_ssq_p);
        cudaGetSymbolAddress((void**)&p_rsq_q, g_rsq_q);
        cudaGetSymbolAddress((void**)&p_rsq_p, g_rsq_p);
        cudaGetSymbolAddress((void**)&p_qh,   g_qh_bf);
        cudaGetSymbolAddress((void**)&p_ph,   g_ph_bf);
        cudaGetSymbolAddress((void**)&p_w,    g_w_bf);
        cudaGetSymbolAddress((void**)&p_Qcb,  g_Qcb);
        cudaGetSymbolAddress((void**)&p_Pcb,  g_Pcb);
        cudaFuncSetAttribute(proj_mma,   cudaFuncAttributeMaxDynamicSharedMemorySize, SMEM_TOTAL);
        cudaFuncSetAttribute(maxsim_mma, cudaFuncAttributeMaxDynamicSharedMemorySize, SMEM_TOTAL);
        cudaStreamCreateWithFlags(&s2, cudaStreamNonBlocking);
        cudaEventCreateWithFlags(&evA, cudaEventDisableTiming);
        cudaEventCreateWithFlags(&evB, cudaEventDisableTiming);
    }

    dim3 gQP(Bp, Bq);

    /* main stream: converts (+ fused sparse token weights) */
    cvt_tw_all<<<Bq*Lq + Bp*Lp, 128>>>(q_hidden, p_hidden, sparse_w, sparse_b,
                                       p_qh, p_ph, p_tw_q, p_tw_p);
    f2bf_kernel<<<(Hd*Hd/4 + 255)/256, 256>>>(colbert_w, p_w, Hd*Hd/4);

    /* fork: independent small kernels on side stream */
    cudaEventRecord(evA, 0);
    cudaStreamWaitEvent(s2, evA, 0);
    dense_kernel<<<gQP, 256, 0, s2>>>(q_hidden, p_hidden, out);
    canon_kernel<<<Bq, Lq, 0, s2>>>(q_ids, p_tw_q, p_wq, Lq);
    canon_kernel<<<Bp, Lp, 0, s2>>>(p_ids, p_tw_p, p_wp, Lp);
    sparse_score_kernel<<<gQP, 256, 0, s2>>>(q_ids, p_wq, p_ids, p_wp, out);
    cudaEventRecord(evB, s2);

    /* main stream: GEMM chain */
    proj_mma<<<dim3(Hd/128, QTILES+PTILES), 128, SMEM_TOTAL>>>(
        p_qh, p_ph, p_w, p_Qcb, p_Pcb, p_ssq_q, p_ssq_p, colbert_b, q_mask, p_mask);
    ssq_reduce<<<(MQ+MP+255)/256, 256>>>(p_ssq_q, p_ssq_p, p_rsq_q, p_rsq_p);
    maxsim_mma<<<dim3(Bp*4, QTILES), 128, SMEM_TOTAL>>>(p_Qcb, p_Pcb, p_rsq_p, p_qmax);

    /* join + final */
    cudaStreamWaitEvent(0, evB, 0);
    colbert_final_kernel<<<gQP, 128>>>(p_qmax, p_rsq_q, q_mask, out);
}